// round 10
// baseline (speedup 1.0000x reference)
#include <cuda_runtime.h>
#include <cuda_bf16.h>
#include <cstdint>

// ---------------------------------------------------------------------------
// Problem constants
// ---------------------------------------------------------------------------
#define TOKENS   100352          // 1024 windows * 98
#define CDIM     512
#define QKVDIM   1536
#define MLPDIM   2048
#define NWINHEAD 16384

typedef unsigned short u16;

// ---------------------------------------------------------------------------
// Scratch (static device arrays)
// ---------------------------------------------------------------------------
__device__ __align__(16) u16   g_hh [(size_t)TOKENS * CDIM];
__device__ __align__(16) u16   g_hl [(size_t)TOKENS * CDIM];
__device__ __align__(16) float g_qkv[(size_t)TOKENS * QKVDIM];
__device__ __align__(16) u16   g_oh [(size_t)TOKENS * CDIM];
__device__ __align__(16) u16   g_ol [(size_t)TOKENS * CDIM];
__device__ __align__(16) float g_attn[(size_t)TOKENS * CDIM];
__device__ __align__(16) u16   g_mh [(size_t)TOKENS * MLPDIM];
__device__ __align__(16) u16   g_ml [(size_t)TOKENS * MLPDIM];
__device__ __align__(16) u16   g_wqkvh[QKVDIM * CDIM], g_wqkvl[QKVDIM * CDIM];
__device__ __align__(16) u16   g_wprh [CDIM * CDIM],   g_wprl [CDIM * CDIM];
__device__ __align__(16) u16   g_w1h  [MLPDIM * CDIM], g_w1l  [MLPDIM * CDIM];
__device__ __align__(16) u16   g_w2h  [CDIM * MLPDIM], g_w2l  [CDIM * MLPDIM];

// ---------------------------------------------------------------------------
// helpers
// ---------------------------------------------------------------------------
__device__ __forceinline__ int w2o(int m) {
    int win = m / 98;
    int n   = m - win * 98;
    int b   = win >> 9;
    int r   = win & 511;
    int wd  = r >> 6;
    int wh  = (r >> 3) & 7;
    int ww  = r & 7;
    int dw  = n / 49;
    int rem = n - dw * 49;
    int hw  = rem / 7;
    int wl  = rem - hw * 7;
    return (((b * 16 + wd * 2 + dw) * 56) + wh * 7 + hw) * 56 + ww * 7 + wl;
}

__device__ __forceinline__ void split1(float x, u16& hi, u16& lo) {
    __nv_bfloat16 h = __float2bfloat16(x);
    float r = x - __bfloat162float(h);
    __nv_bfloat16 l = __float2bfloat16(r);
    hi = *reinterpret_cast<u16*>(&h);
    lo = *reinterpret_cast<u16*>(&l);
}

__device__ __forceinline__ void split2(float x0, float x1, unsigned& hi, unsigned& lo) {
    unsigned h;
    asm("cvt.rn.bf16x2.f32 %0, %1, %2;" : "=r"(h) : "f"(x1), "f"(x0));
    float h0 = __uint_as_float(h << 16);
    float h1 = __uint_as_float(h & 0xffff0000u);
    unsigned l;
    asm("cvt.rn.bf16x2.f32 %0, %1, %2;" : "=r"(l) : "f"(x1 - h1), "f"(x0 - h0));
    hi = h; lo = l;
}

__device__ __forceinline__ float gelu_tanh(float x) {
    float u = 0.7978845608028654f * (x + 0.044715f * x * x * x);
    return 0.5f * x * (1.f + tanhf(u));
}

__device__ __forceinline__ void cpasync16(unsigned dst, const void* src) {
    asm volatile("cp.async.cg.shared.global [%0], [%1], 16;" :: "r"(dst), "l"(src));
}

__device__ __forceinline__ void ldsm4(unsigned r[4], unsigned addr) {
    asm volatile("ldmatrix.sync.aligned.m8n8.x4.shared.b16 {%0,%1,%2,%3}, [%4];"
                 : "=r"(r[0]), "=r"(r[1]), "=r"(r[2]), "=r"(r[3]) : "r"(addr));
}

__device__ __forceinline__ void mma16(float c[4], const unsigned a[4], const unsigned b[2]) {
    asm volatile(
        "mma.sync.aligned.m16n8k16.row.col.f32.bf16.bf16.f32 "
        "{%0,%1,%2,%3},{%4,%5,%6,%7},{%8,%9},{%0,%1,%2,%3};"
        : "+f"(c[0]), "+f"(c[1]), "+f"(c[2]), "+f"(c[3])
        : "r"(a[0]), "r"(a[1]), "r"(a[2]), "r"(a[3]), "r"(b[0]), "r"(b[1]));
}

// ---------------------------------------------------------------------------
// Weight convert + transpose: w[K][N] fp32 -> [N][K] bf16 hi/lo
// ---------------------------------------------------------------------------
__global__ void wconv_kernel(const float* __restrict__ w, u16* __restrict__ th,
                             u16* __restrict__ tl, int K, int N)
{
    __shared__ float tile[32][33];
    int n0 = blockIdx.x * 32, k0 = blockIdx.y * 32;
    int tx = threadIdx.x, ty = threadIdx.y;
#pragma unroll
    for (int r = 0; r < 4; ++r)
        tile[ty + 8 * r][tx] = w[(size_t)(k0 + ty + 8 * r) * N + n0 + tx];
    __syncthreads();
#pragma unroll
    for (int r = 0; r < 4; ++r) {
        int n = n0 + ty + 8 * r, k = k0 + tx;
        u16 h, l; split1(tile[tx][ty + 8 * r], h, l);
        th[(size_t)n * K + k] = h;
        tl[(size_t)n * K + k] = l;
    }
}

// ---------------------------------------------------------------------------
// LayerNorm -> bf16 hi/lo
// ---------------------------------------------------------------------------
__global__ void ln_kernel(const float* __restrict__ x, const float* __restrict__ g,
                          const float* __restrict__ b, u16* __restrict__ oh,
                          u16* __restrict__ ol, int gather)
{
    int row  = blockIdx.x * 8 + (threadIdx.x >> 5);
    int lane = threadIdx.x & 31;
    if (row >= TOKENS) return;
    int src = gather ? w2o(row) : row;
    const float* xr = x + (size_t)src * CDIM;

    float v[16], s = 0.f, ss = 0.f;
#pragma unroll
    for (int k = 0; k < 16; ++k) {
        float a = xr[lane + 32 * k];
        v[k] = a; s += a; ss += a * a;
    }
#pragma unroll
    for (int off = 16; off; off >>= 1) {
        s  += __shfl_xor_sync(0xffffffffu, s,  off);
        ss += __shfl_xor_sync(0xffffffffu, ss, off);
    }
    float mu   = s * (1.f / 512.f);
    float rstd = rsqrtf(ss * (1.f / 512.f) - mu * mu + 1e-5f);

    size_t ro = (size_t)row * CDIM;
#pragma unroll
    for (int k = 0; k < 16; ++k) {
        int c = lane + 32 * k;
        u16 h, l; split1((v[k] - mu) * rstd * g[c] + b[c], h, l);
        oh[ro + c] = h; ol[ro + c] = l;
    }
}

// ---------------------------------------------------------------------------
// BF16x2 GEMM v4 (legacy mma.sync; sm_100 target has no tcgen05):
//   A: [M][K] bf16 (hi,lo)    B: [N][K] bf16 (hi,lo)
// 128x128 tile, BK=32, 3-stage cp.async ring, 256 thr, warps 2x4, wt 64x32.
// Stage (32KB): Ahi[128][32] | Alo | Bhi[128][32] | Blo, rows 64B, XOR swizzle.
// MMA: m16n8k16 bf16, 3 terms. v4: each term is a FULL (i,j) pass so the
// reuse distance on every accumulator is 16 MMAs (was 1 -> RAW-stall bound).
// ---------------------------------------------------------------------------
#define STG32    32768
#define OFF_ALO  8192
#define OFF_BHI  16384
#define OFF_BLO  24576
#define GEMM_DSM (3 * STG32)     // 96KB dynamic

__device__ __forceinline__ unsigned swz64(int row, int c) {
    return (unsigned)(row * 64 + ((c ^ ((row >> 1) & 3)) << 4));
}

// thread t: 2 chunks per array; chunk ch -> row = ch>>2, c = ch&3
__device__ __forceinline__ void load_stage(unsigned sb,
    const u16* __restrict__ Ah, const u16* __restrict__ Al,
    const u16* __restrict__ Bh, const u16* __restrict__ Bl,
    int K, int bm, int bn, int kt, int t)
{
#pragma unroll
    for (int i = 0; i < 2; ++i) {
        int ch = t * 2 + i;
        int row = ch >> 2, c = ch & 3;
        unsigned so = swz64(row, c);
        size_t ga = (size_t)(bm + row) * K + kt * 32 + c * 8;
        size_t gb = (size_t)(bn + row) * K + kt * 32 + c * 8;
        cpasync16(sb + so,           Ah + ga);
        cpasync16(sb + OFF_ALO + so, Al + ga);
        cpasync16(sb + OFF_BHI + so, Bh + gb);
        cpasync16(sb + OFF_BLO + so, Bl + gb);
    }
}

// one k16 half (kk = 0/1) from a stage; 3 dependency-separated passes
__device__ __forceinline__ void compute_k16(unsigned base, int kk,
                                            int wm, int wn, int lane, float c[4][4][4])
{
    int mat  = lane >> 3;
    int rsub = lane & 7;
    int aRow = (mat & 1) * 8 + rsub;  int aCh = kk * 2 + (mat >> 1);
    int bRow = (mat >> 1) * 8 + rsub; int bCh = kk * 2 + (mat & 1);

    unsigned Ahi[4][4], Bhi[2][4], Blo[2][4];
#pragma unroll
    for (int i = 0; i < 4; ++i)
        ldsm4(Ahi[i], base + swz64(wm * 64 + i * 16 + aRow, aCh));
#pragma unroll
    for (int g = 0; g < 2; ++g) {
        int r = wn * 32 + g * 16 + bRow;
        ldsm4(Bhi[g], base + OFF_BHI + swz64(r, bCh));
        ldsm4(Blo[g], base + OFF_BLO + swz64(r, bCh));
    }
    // pass 1: Ah*Bh — each accumulator touched exactly once
#pragma unroll
    for (int i = 0; i < 4; ++i)
#pragma unroll
        for (int j = 0; j < 4; ++j)
            mma16(c[i][j], Ahi[i], &Bhi[j >> 1][(j & 1) * 2]);
    // pass 2: Ah*Bl — reuse distance 16 from pass 1
#pragma unroll
    for (int i = 0; i < 4; ++i)
#pragma unroll
        for (int j = 0; j < 4; ++j)
            mma16(c[i][j], Ahi[i], &Blo[j >> 1][(j & 1) * 2]);
    // pass 3: Al*Bh — Alo loaded late (Ahi/Blo dead by now, reg cap holds)
    unsigned Alo[4][4];
#pragma unroll
    for (int i = 0; i < 4; ++i)
        ldsm4(Alo[i], base + OFF_ALO + swz64(wm * 64 + i * 16 + aRow, aCh));
#pragma unroll
    for (int i = 0; i < 4; ++i)
#pragma unroll
        for (int j = 0; j < 4; ++j)
            mma16(c[i][j], Alo[i], &Bhi[j >> 1][(j & 1) * 2]);
}

// EPI: 0 = +bias -> fp32 ; 1 = +bias,gelu -> bf16 hi/lo ; 2 = +bias+res, w2o scatter
template <int EPI>
__global__ void __launch_bounds__(256, 2)
gemm_bf16(const u16* __restrict__ Ah, const u16* __restrict__ Al,
          const u16* __restrict__ Bh, const u16* __restrict__ Bl,
          const float* __restrict__ bias, const float* __restrict__ res,
          float* __restrict__ Cf, u16* __restrict__ Ch, u16* __restrict__ Cl,
          int N, int K)
{
    extern __shared__ char sm_raw[];
    unsigned sb = (unsigned)__cvta_generic_to_shared(sm_raw);

    int t = threadIdx.x;
    int warp = t >> 5, lane = t & 31;
    int wm = warp >> 2, wn = warp & 3;
    int bm = blockIdx.y * 128, bn = blockIdx.x * 128;

    float c[4][4][4];
#pragma unroll
    for (int i = 0; i < 4; ++i)
#pragma unroll
        for (int j = 0; j < 4; ++j)
#pragma unroll
            for (int k = 0; k < 4; ++k) c[i][j][k] = 0.f;

    int KT = K >> 5;                     // BK = 32
    load_stage(sb,         Ah, Al, Bh, Bl, K, bm, bn, 0, t);
    asm volatile("cp.async.commit_group;" ::: "memory");
    load_stage(sb + STG32, Ah, Al, Bh, Bl, K, bm, bn, 1, t);
    asm volatile("cp.async.commit_group;" ::: "memory");

    for (int kt = 0; kt < KT; ++kt) {
        if (kt + 1 < KT) asm volatile("cp.async.wait_group 1;" ::: "memory");
        else             asm volatile("cp.async.wait_group 0;" ::: "memory");
        __syncthreads();
        if (kt + 2 < KT) {
            load_stage(sb + (unsigned)((kt + 2) % 3) * STG32,
                       Ah, Al, Bh, Bl, K, bm, bn, kt + 2, t);
            asm volatile("cp.async.commit_group;" ::: "memory");
        }
        unsigned base = sb + (unsigned)(kt % 3) * STG32;
        compute_k16(base, 0, wm, wn, lane, c);
        compute_k16(base, 1, wm, wn, lane, c);
    }

    // epilogue (C frag: rows r0,r0+8 ; cols col,col+1)
#pragma unroll
    for (int i = 0; i < 4; ++i) {
        int r0 = bm + wm * 64 + i * 16 + (lane >> 2);
        int rows[2] = { r0, r0 + 8 };
        int dst[2];
        if (EPI == 2) { dst[0] = w2o(rows[0]); dst[1] = w2o(rows[1]); }
#pragma unroll
        for (int j = 0; j < 4; ++j) {
            int col = bn + wn * 32 + j * 8 + ((lane & 3) << 1);
            float bv0 = bias[col], bv1 = bias[col + 1];
#pragma unroll
            for (int rr = 0; rr < 2; ++rr) {
                float v0 = c[i][j][rr * 2 + 0] + bv0;
                float v1 = c[i][j][rr * 2 + 1] + bv1;
                if (EPI == 0) {
                    size_t oo = (size_t)rows[rr] * (size_t)N + col;
                    Cf[oo] = v0; Cf[oo + 1] = v1;
                } else if (EPI == 1) {
                    v0 = gelu_tanh(v0); v1 = gelu_tanh(v1);
                    unsigned h, l; split2(v0, v1, h, l);
                    size_t oo = (size_t)rows[rr] * (size_t)N + col;
                    *reinterpret_cast<unsigned*>(Ch + oo) = h;
                    *reinterpret_cast<unsigned*>(Cl + oo) = l;
                } else {
                    size_t ro = (size_t)rows[rr] * CDIM + col;
                    v0 += res[ro]; v1 += res[ro + 1];
                    size_t oo = (size_t)dst[rr] * CDIM + col;
                    Cf[oo] = v0; Cf[oo + 1] = v1;
                }
            }
        }
    }
}

// ---------------------------------------------------------------------------
// Windowed attention: one CTA per (window, head). fp32 SIMT.
// ---------------------------------------------------------------------------
#define SQ_OFF  0
#define SK_OFF  3136
#define SVT_OFF (3136 + 3528)
#define SP_OFF  (SVT_OFF + 3200)
#define ATTN_SMEM_BYTES ((SP_OFF + 9800) * 4)

__global__ void __launch_bounds__(128)
attn_kernel(const float* __restrict__ qkv, u16* __restrict__ oh, u16* __restrict__ ol)
{
    extern __shared__ float sm[];
    float* sQ  = sm + SQ_OFF;
    float* sK  = sm + SK_OFF;
    float* sVt = sm + SVT_OFF;
    float* sP  = sm + SP_OFF;

    int win  = blockIdx.x >> 4;
    int head = blockIdx.x & 15;
    int t = threadIdx.x, warp = t >> 5, lane = t & 31;

    if (t < 64) sVt[(t >> 1) * 100 + 98 + (t & 1)] = 0.f;

    const float scale = 0.17677669529663687f;
    size_t base = (size_t)win * 98 * QKVDIM + (size_t)head * 32;
    for (int idx = t; idx < 98 * 32; idx += 128) {
        int n = idx >> 5, hd = idx & 31;
        const float* p = qkv + base + (size_t)n * QKVDIM + hd;
        sQ[n * 32 + hd]   = p[0] * scale;
        sK[n * 36 + hd]   = p[512];
        sVt[hd * 100 + n] = p[1024];
    }
    __syncthreads();

    for (int i = warp; i < 98; i += 4) {
        float4 q4[8];
        const float4* qrow = (const float4*)(sQ + i * 32);
#pragma unroll
        for (int cc = 0; cc < 8; ++cc) q4[cc] = qrow[cc];

        float sv[4];
        float mx = -1e30f;
#pragma unroll
        for (int jj = 0; jj < 4; ++jj) {
            int j = lane + jj * 32;
            float a = -1e30f;
            if (j < 98) {
                const float4* krow = (const float4*)(sK + j * 36);
                float acc = 0.f;
#pragma unroll
                for (int cc = 0; cc < 8; ++cc) {
                    float4 k4 = krow[cc];
                    acc += q4[cc].x * k4.x + q4[cc].y * k4.y
                         + q4[cc].z * k4.z + q4[cc].w * k4.w;
                }
                a = acc;
            }
            sv[jj] = a;
            mx = fmaxf(mx, a);
        }
#pragma unroll
        for (int off = 16; off; off >>= 1)
            mx = fmaxf(mx, __shfl_xor_sync(0xffffffffu, mx, off));
        float sum = 0.f;
#pragma unroll
        for (int jj = 0; jj < 4; ++jj) {
            int j = lane + jj * 32;
            float e = (j < 98) ? __expf(sv[jj] - mx) : 0.f;
            sv[jj] = e; sum += e;
        }
#pragma unroll
        for (int off = 16; off; off >>= 1)
            sum += __shfl_xor_sync(0xffffffffu, sum, off);
        float inv = 1.f / sum;
#pragma unroll
        for (int jj = 0; jj < 4; ++jj) {
            int j = lane + jj * 32;
            if (j < 98) sP[i * 100 + j] = sv[jj] * inv;
        }
        if (lane < 2) sP[i * 100 + 98 + lane] = 0.f;
    }
    __syncthreads();

    size_t obase = (size_t)win * 98 * CDIM + (size_t)head * 32 + lane;
    const float4* vrow = (const float4*)(sVt + lane * 100);
    for (int i = warp; i < 98; i += 4) {
        const float4* prow = (const float4*)(sP + i * 100);
        float acc = 0.f;
#pragma unroll
        for (int cc = 0; cc < 25; ++cc) {
            float4 p4 = prow[cc];
            float4 v4 = vrow[cc];
            acc += p4.x * v4.x + p4.y * v4.y + p4.z * v4.z + p4.w * v4.w;
        }
        u16 h, l; split1(acc, h, l);
        oh[obase + (size_t)i * CDIM] = h;
        ol[obase + (size_t)i * CDIM] = l;
    }
}

// ---------------------------------------------------------------------------
// launch
// ---------------------------------------------------------------------------
extern "C" void kernel_launch(void* const* d_in, const int* in_sizes, int n_in,
                              void* d_out, int out_size)
{
    (void)in_sizes; (void)n_in; (void)out_size;

    const float* x     = (const float*)d_in[0];
    const float* g1    = (const float*)d_in[1];
    const float* b1    = (const float*)d_in[2];
    const float* wqkv  = (const float*)d_in[3];
    const float* bqkv  = (const float*)d_in[4];
    const float* wproj = (const float*)d_in[5];
    const float* bproj = (const float*)d_in[6];
    const float* g2    = (const float*)d_in[7];
    const float* b2    = (const float*)d_in[8];
    const float* w1    = (const float*)d_in[9];
    const float* bm1   = (const float*)d_in[10];
    const float* w2    = (const float*)d_in[11];
    const float* bm2   = (const float*)d_in[12];
    float* out = (float*)d_out;

    u16 *hh, *hl, *oh, *ol, *mh, *ml;
    u16 *wqh, *wql, *wph, *wpl, *w1h, *w1l, *w2h, *w2l;
    float *qkv, *attn;
    cudaGetSymbolAddress((void**)&hh,  g_hh);   cudaGetSymbolAddress((void**)&hl,  g_hl);
    cudaGetSymbolAddress((void**)&qkv, g_qkv);
    cudaGetSymbolAddress((void**)&oh,  g_oh);   cudaGetSymbolAddress((void**)&ol,  g_ol);
    cudaGetSymbolAddress((void**)&attn,g_attn);
    cudaGetSymbolAddress((void**)&mh,  g_mh);   cudaGetSymbolAddress((void**)&ml,  g_ml);
    cudaGetSymbolAddress((void**)&wqh, g_wqkvh); cudaGetSymbolAddress((void**)&wql, g_wqkvl);
    cudaGetSymbolAddress((void**)&wph, g_wprh);  cudaGetSymbolAddress((void**)&wpl, g_wprl);
    cudaGetSymbolAddress((void**)&w1h, g_w1h);   cudaGetSymbolAddress((void**)&w1l, g_w1l);
    cudaGetSymbolAddress((void**)&w2h, g_w2h);   cudaGetSymbolAddress((void**)&w2l, g_w2l);

    cudaFuncSetAttribute((const void*)attn_kernel,
                         cudaFuncAttributeMaxDynamicSharedMemorySize, ATTN_SMEM_BYTES);
    cudaFuncSetAttribute((const void*)gemm_bf16<0>,
                         cudaFuncAttributeMaxDynamicSharedMemorySize, GEMM_DSM);
    cudaFuncSetAttribute((const void*)gemm_bf16<1>,
                         cudaFuncAttributeMaxDynamicSharedMemorySize, GEMM_DSM);
    cudaFuncSetAttribute((const void*)gemm_bf16<2>,
                         cudaFuncAttributeMaxDynamicSharedMemorySize, GEMM_DSM);

    dim3 wblk(32, 8);
    wconv_kernel<<<dim3(QKVDIM / 32, CDIM / 32), wblk>>>(wqkv, wqh, wql, CDIM, QKVDIM);
    wconv_kernel<<<dim3(CDIM / 32, CDIM / 32),   wblk>>>(wproj, wph, wpl, CDIM, CDIM);
    wconv_kernel<<<dim3(MLPDIM / 32, CDIM / 32), wblk>>>(w1, w1h, w1l, CDIM, MLPDIM);
    wconv_kernel<<<dim3(CDIM / 32, MLPDIM / 32), wblk>>>(w2, w2h, w2l, MLPDIM, CDIM);

    const int LN_BLOCKS = TOKENS / 8;
    const int MT = TOKENS / 128;   // 784

    // 1. window-partition gather + LN1
    ln_kernel<<<LN_BLOCKS, 256>>>(x, g1, b1, hh, hl, 1);

    // 2. qkv = h @ wqkv + bqkv (fp32)
    gemm_bf16<0><<<dim3(QKVDIM / 128, MT), 256, GEMM_DSM>>>(
        hh, hl, wqh, wql, bqkv, nullptr, qkv, nullptr, nullptr, QKVDIM, CDIM);

    // 3. windowed attention
    attn_kernel<<<NWINHEAD, 128, ATTN_SMEM_BYTES>>>(qkv, oh, ol);

    // 4. attn = o @ wproj + bproj (fp32)
    gemm_bf16<0><<<dim3(CDIM / 128, MT), 256, GEMM_DSM>>>(
        oh, ol, wph, wpl, bproj, nullptr, attn, nullptr, nullptr, CDIM, CDIM);

    // 5. LN2
    ln_kernel<<<LN_BLOCKS, 256>>>(attn, g2, b2, hh, hl, 0);

    // 6. hidden = gelu(h @ w1 + bm1) (bf16 hi/lo)
    gemm_bf16<1><<<dim3(MLPDIM / 128, MT), 256, GEMM_DSM>>>(
        hh, hl, w1h, w1l, bm1, nullptr, nullptr, mh, ml, MLPDIM, CDIM);

    // 7. out[w2o(m)] = attn[m] + hidden[m] @ w2 + bm2
    gemm_bf16<2><<<dim3(CDIM / 128, MT), 256, GEMM_DSM>>>(
        mh, ml, w2h, w2l, bm2, attn, out, nullptr, nullptr, CDIM, MLPDIM);
}

// round 11
// speedup vs baseline: 1.2140x; 1.2140x over previous
#include <cuda_runtime.h>
#include <cstdint>

// ---------------------------------------------------------------------------
// Problem constants
// ---------------------------------------------------------------------------
#define TOKENS   100352          // 1024 windows * 98
#define CDIM     512
#define QKVDIM   1536
#define MLPDIM   2048
#define NWINHEAD 16384

// ---------------------------------------------------------------------------
// Scratch (static device arrays). All GEMM operands are tf32-rounded fp32.
// ---------------------------------------------------------------------------
__device__ __align__(16) float g_h   [(size_t)TOKENS * CDIM];    // LN out (tf32)
__device__ __align__(16) float g_qkv [(size_t)TOKENS * QKVDIM];  // fp32
__device__ __align__(16) float g_o   [(size_t)TOKENS * CDIM];    // attn out (tf32)
__device__ __align__(16) float g_attn[(size_t)TOKENS * CDIM];    // proj out fp32
__device__ __align__(16) float g_m   [(size_t)TOKENS * MLPDIM];  // gelu out (tf32)
__device__ __align__(16) float g_wq  [QKVDIM * CDIM];            // [N][K] tf32
__device__ __align__(16) float g_wp  [CDIM * CDIM];
__device__ __align__(16) float g_w1  [MLPDIM * CDIM];
__device__ __align__(16) float g_w2  [CDIM * MLPDIM];

// ---------------------------------------------------------------------------
// helpers
// ---------------------------------------------------------------------------
__device__ __forceinline__ int w2o(int m) {
    int win = m / 98;
    int n   = m - win * 98;
    int b   = win >> 9;
    int r   = win & 511;
    int wd  = r >> 6;
    int wh  = (r >> 3) & 7;
    int ww  = r & 7;
    int dw  = n / 49;
    int rem = n - dw * 49;
    int hw  = rem / 7;
    int wl  = rem - hw * 7;
    return (((b * 16 + wd * 2 + dw) * 56) + wh * 7 + hw) * 56 + ww * 7 + wl;
}

__device__ __forceinline__ float to_tf32(float x) {
    unsigned u;
    asm("cvt.rna.tf32.f32 %0, %1;" : "=r"(u) : "f"(x));
    return __uint_as_float(u);
}

__device__ __forceinline__ float gelu_tanh(float x) {
    float u = 0.7978845608028654f * (x + 0.044715f * x * x * x);
    return 0.5f * x * (1.f + tanhf(u));
}

__device__ __forceinline__ void cpasync16(unsigned dst, const void* src) {
    asm volatile("cp.async.cg.shared.global [%0], [%1], 16;" :: "r"(dst), "l"(src));
}

__device__ __forceinline__ void mma8(float c[4], const float a[4], const float b[2]) {
    asm volatile(
        "mma.sync.aligned.m16n8k8.row.col.f32.tf32.tf32.f32 "
        "{%0,%1,%2,%3},{%4,%5,%6,%7},{%8,%9},{%0,%1,%2,%3};"
        : "+f"(c[0]), "+f"(c[1]), "+f"(c[2]), "+f"(c[3])
        : "r"(__float_as_uint(a[0])), "r"(__float_as_uint(a[1])),
          "r"(__float_as_uint(a[2])), "r"(__float_as_uint(a[3])),
          "r"(__float_as_uint(b[0])), "r"(__float_as_uint(b[1])));
}

// ---------------------------------------------------------------------------
// Weight convert + transpose: w[K][N] fp32 -> [N][K] tf32
// ---------------------------------------------------------------------------
__global__ void wconv_kernel(const float* __restrict__ w, float* __restrict__ wt,
                             int K, int N)
{
    __shared__ float tile[32][33];
    int n0 = blockIdx.x * 32, k0 = blockIdx.y * 32;
    int tx = threadIdx.x, ty = threadIdx.y;
#pragma unroll
    for (int r = 0; r < 4; ++r)
        tile[ty + 8 * r][tx] = w[(size_t)(k0 + ty + 8 * r) * N + n0 + tx];
    __syncthreads();
#pragma unroll
    for (int r = 0; r < 4; ++r) {
        int n = n0 + ty + 8 * r, k = k0 + tx;
        wt[(size_t)n * K + k] = to_tf32(tile[tx][ty + 8 * r]);
    }
}

// ---------------------------------------------------------------------------
// LayerNorm -> tf32
// ---------------------------------------------------------------------------
__global__ void ln_kernel(const float* __restrict__ x, const float* __restrict__ g,
                          const float* __restrict__ b, float* __restrict__ o,
                          int gather)
{
    int row  = blockIdx.x * 8 + (threadIdx.x >> 5);
    int lane = threadIdx.x & 31;
    if (row >= TOKENS) return;
    int src = gather ? w2o(row) : row;
    const float* xr = x + (size_t)src * CDIM;

    float v[16], s = 0.f, ss = 0.f;
#pragma unroll
    for (int k = 0; k < 16; ++k) {
        float a = xr[lane + 32 * k];
        v[k] = a; s += a; ss += a * a;
    }
#pragma unroll
    for (int off = 16; off; off >>= 1) {
        s  += __shfl_xor_sync(0xffffffffu, s,  off);
        ss += __shfl_xor_sync(0xffffffffu, ss, off);
    }
    float mu   = s * (1.f / 512.f);
    float rstd = rsqrtf(ss * (1.f / 512.f) - mu * mu + 1e-5f);

    size_t ro = (size_t)row * CDIM;
#pragma unroll
    for (int k = 0; k < 16; ++k) {
        int c = lane + 32 * k;
        o[ro + c] = to_tf32((v[k] - mu) * rstd * g[c] + b[c]);
    }
}

// ---------------------------------------------------------------------------
// TF32 single-pass GEMM v5 (instruction-minimal for the legacy HMMA pipe):
//   A: [M][K] tf32-rounded fp32    B: [N][K] tf32-rounded fp32
// 128x128 tile, BK=32, 3-stage cp.async ring, 256 thr, warps 2x4, wt 64x32.
// Stage (36KB): A[128][36] fp32 | B[128][36] fp32  (36-float padded rows ->
// scalar-LDS fragment loads are verified conflict-free: bank = 4*(lane>>2)
// + (lane&3) + 8*s mod 32, all distinct; +4-col frags likewise).
// MMA: m16n8k8 tf32, ONE term. 308M instr vs 462M for bf16x3.
// ---------------------------------------------------------------------------
#define PADF     36
#define TILEB    (128 * PADF * 4)     // 18432 B
#define OFF_B    TILEB
#define STGB     (2 * TILEB)          // 36864 B
#define GEMM_DSM (3 * STGB)           // 110592 B

// A/B tiles: 1024 16B chunks each; thread t loads 4 of each (coalesced).
__device__ __forceinline__ void load_stage(unsigned sb,
    const float* __restrict__ A, const float* __restrict__ B,
    int K, int bm, int bn, int kt, int t)
{
#pragma unroll
    for (int i = 0; i < 4; ++i) {
        int ch = t + 256 * i;
        int row = ch >> 3, c = ch & 7;
        unsigned so = (unsigned)(row * (PADF * 4) + c * 16);
        cpasync16(sb + so,         A + (size_t)(bm + row) * K + kt * 32 + c * 4);
        cpasync16(sb + OFF_B + so, B + (size_t)(bn + row) * K + kt * 32 + c * 4);
    }
}

// one k8 step (s = 0..3) from a stage
__device__ __forceinline__ void compute_k8(const float* sA, const float* sB, int s,
                                           int wm, int wn, int lane, float c[4][4][4])
{
    int qr = lane >> 2;      // 0..7
    int qc = lane & 3;       // 0..3
    float a[4][4];
#pragma unroll
    for (int i = 0; i < 4; ++i) {
        int base = (wm * 64 + i * 16 + qr) * PADF + s * 8 + qc;
        a[i][0] = sA[base];
        a[i][1] = sA[base + 8 * PADF];
        a[i][2] = sA[base + 4];
        a[i][3] = sA[base + 8 * PADF + 4];
    }
    float b[4][2];
#pragma unroll
    for (int j = 0; j < 4; ++j) {
        int base = (wn * 32 + j * 8 + qr) * PADF + s * 8 + qc;
        b[j][0] = sB[base];
        b[j][1] = sB[base + 4];
    }
#pragma unroll
    for (int i = 0; i < 4; ++i)
#pragma unroll
        for (int j = 0; j < 4; ++j)
            mma8(c[i][j], a[i], b[j]);
}

// EPI: 0 = +bias -> fp32 ; 1 = +bias,gelu -> tf32 ; 2 = +bias+res, w2o scatter
template <int EPI>
__global__ void __launch_bounds__(256, 2)
gemm_tf32(const float* __restrict__ A, const float* __restrict__ B,
          const float* __restrict__ bias, const float* __restrict__ res,
          float* __restrict__ C, int N, int K)
{
    extern __shared__ char sm_raw[];
    unsigned sb = (unsigned)__cvta_generic_to_shared(sm_raw);

    int t = threadIdx.x;
    int warp = t >> 5, lane = t & 31;
    int wm = warp >> 2, wn = warp & 3;
    int bm = blockIdx.y * 128, bn = blockIdx.x * 128;

    float c[4][4][4];
#pragma unroll
    for (int i = 0; i < 4; ++i)
#pragma unroll
        for (int j = 0; j < 4; ++j)
#pragma unroll
            for (int k = 0; k < 4; ++k) c[i][j][k] = 0.f;

    int KT = K >> 5;                     // BK = 32
    load_stage(sb,        A, B, K, bm, bn, 0, t);
    asm volatile("cp.async.commit_group;" ::: "memory");
    load_stage(sb + STGB, A, B, K, bm, bn, 1, t);
    asm volatile("cp.async.commit_group;" ::: "memory");

    for (int kt = 0; kt < KT; ++kt) {
        if (kt + 1 < KT) asm volatile("cp.async.wait_group 1;" ::: "memory");
        else             asm volatile("cp.async.wait_group 0;" ::: "memory");
        __syncthreads();
        if (kt + 2 < KT) {
            load_stage(sb + (unsigned)((kt + 2) % 3) * STGB,
                       A, B, K, bm, bn, kt + 2, t);
            asm volatile("cp.async.commit_group;" ::: "memory");
        }
        const float* sA = (const float*)(sm_raw + (size_t)(kt % 3) * STGB);
        const float* sB = (const float*)(sm_raw + (size_t)(kt % 3) * STGB + OFF_B);
        compute_k8(sA, sB, 0, wm, wn, lane, c);
        compute_k8(sA, sB, 1, wm, wn, lane, c);
        compute_k8(sA, sB, 2, wm, wn, lane, c);
        compute_k8(sA, sB, 3, wm, wn, lane, c);
    }

    // epilogue (C frag: rows r0,r0+8 ; cols col,col+1)
#pragma unroll
    for (int i = 0; i < 4; ++i) {
        int r0 = bm + wm * 64 + i * 16 + (lane >> 2);
        int rows[2] = { r0, r0 + 8 };
        int dst[2];
        if (EPI == 2) { dst[0] = w2o(rows[0]); dst[1] = w2o(rows[1]); }
#pragma unroll
        for (int j = 0; j < 4; ++j) {
            int col = bn + wn * 32 + j * 8 + ((lane & 3) << 1);
            float bv0 = bias[col], bv1 = bias[col + 1];
#pragma unroll
            for (int rr = 0; rr < 2; ++rr) {
                float v0 = c[i][j][rr * 2 + 0] + bv0;
                float v1 = c[i][j][rr * 2 + 1] + bv1;
                if (EPI == 0) {
                    size_t oo = (size_t)rows[rr] * (size_t)N + col;
                    C[oo] = v0; C[oo + 1] = v1;
                } else if (EPI == 1) {
                    size_t oo = (size_t)rows[rr] * (size_t)N + col;
                    C[oo]     = to_tf32(gelu_tanh(v0));
                    C[oo + 1] = to_tf32(gelu_tanh(v1));
                } else {
                    size_t ro = (size_t)rows[rr] * CDIM + col;
                    v0 += res[ro]; v1 += res[ro + 1];
                    size_t oo = (size_t)dst[rr] * CDIM + col;
                    C[oo] = v0; C[oo + 1] = v1;
                }
            }
        }
    }
}

// ---------------------------------------------------------------------------
// Windowed attention: one CTA per (window, head). fp32 SIMT. Out = tf32.
// ---------------------------------------------------------------------------
#define SQ_OFF  0
#define SK_OFF  3136
#define SVT_OFF (3136 + 3528)
#define SP_OFF  (SVT_OFF + 3200)
#define ATTN_SMEM_BYTES ((SP_OFF + 9800) * 4)

__global__ void __launch_bounds__(128)
attn_kernel(const float* __restrict__ qkv, float* __restrict__ o)
{
    extern __shared__ float sm[];
    float* sQ  = sm + SQ_OFF;
    float* sK  = sm + SK_OFF;
    float* sVt = sm + SVT_OFF;
    float* sP  = sm + SP_OFF;

    int win  = blockIdx.x >> 4;
    int head = blockIdx.x & 15;
    int t = threadIdx.x, warp = t >> 5, lane = t & 31;

    if (t < 64) sVt[(t >> 1) * 100 + 98 + (t & 1)] = 0.f;

    const float scale = 0.17677669529663687f;
    size_t base = (size_t)win * 98 * QKVDIM + (size_t)head * 32;
    for (int idx = t; idx < 98 * 32; idx += 128) {
        int n = idx >> 5, hd = idx & 31;
        const float* p = qkv + base + (size_t)n * QKVDIM + hd;
        sQ[n * 32 + hd]   = p[0] * scale;
        sK[n * 36 + hd]   = p[512];
        sVt[hd * 100 + n] = p[1024];
    }
    __syncthreads();

    for (int i = warp; i < 98; i += 4) {
        float4 q4[8];
        const float4* qrow = (const float4*)(sQ + i * 32);
#pragma unroll
        for (int cc = 0; cc < 8; ++cc) q4[cc] = qrow[cc];

        float sv[4];
        float mx = -1e30f;
#pragma unroll
        for (int jj = 0; jj < 4; ++jj) {
            int j = lane + jj * 32;
            float a = -1e30f;
            if (j < 98) {
                const float4* krow = (const float4*)(sK + j * 36);
                float acc = 0.f;
#pragma unroll
                for (int cc = 0; cc < 8; ++cc) {
                    float4 k4 = krow[cc];
                    acc += q4[cc].x * k4.x + q4[cc].y * k4.y
                         + q4[cc].z * k4.z + q4[cc].w * k4.w;
                }
                a = acc;
            }
            sv[jj] = a;
            mx = fmaxf(mx, a);
        }
#pragma unroll
        for (int off = 16; off; off >>= 1)
            mx = fmaxf(mx, __shfl_xor_sync(0xffffffffu, mx, off));
        float sum = 0.f;
#pragma unroll
        for (int jj = 0; jj < 4; ++jj) {
            int j = lane + jj * 32;
            float e = (j < 98) ? __expf(sv[jj] - mx) : 0.f;
            sv[jj] = e; sum += e;
        }
#pragma unroll
        for (int off = 16; off; off >>= 1)
            sum += __shfl_xor_sync(0xffffffffu, sum, off);
        float inv = 1.f / sum;
#pragma unroll
        for (int jj = 0; jj < 4; ++jj) {
            int j = lane + jj * 32;
            if (j < 98) sP[i * 100 + j] = sv[jj] * inv;
        }
        if (lane < 2) sP[i * 100 + 98 + lane] = 0.f;
    }
    __syncthreads();

    size_t obase = (size_t)win * 98 * CDIM + (size_t)head * 32 + lane;
    const float4* vrow = (const float4*)(sVt + lane * 100);
    for (int i = warp; i < 98; i += 4) {
        const float4* prow = (const float4*)(sP + i * 100);
        float acc = 0.f;
#pragma unroll
        for (int cc = 0; cc < 25; ++cc) {
            float4 p4 = prow[cc];
            float4 v4 = vrow[cc];
            acc += p4.x * v4.x + p4.y * v4.y + p4.z * v4.z + p4.w * v4.w;
        }
        o[obase + (size_t)i * CDIM] = to_tf32(acc);
    }
}

// ---------------------------------------------------------------------------
// launch
// ---------------------------------------------------------------------------
extern "C" void kernel_launch(void* const* d_in, const int* in_sizes, int n_in,
                              void* d_out, int out_size)
{
    (void)in_sizes; (void)n_in; (void)out_size;

    const float* x     = (const float*)d_in[0];
    const float* g1    = (const float*)d_in[1];
    const float* b1    = (const float*)d_in[2];
    const float* wqkv  = (const float*)d_in[3];
    const float* bqkv  = (const float*)d_in[4];
    const float* wproj = (const float*)d_in[5];
    const float* bproj = (const float*)d_in[6];
    const float* g2    = (const float*)d_in[7];
    const float* b2    = (const float*)d_in[8];
    const float* w1    = (const float*)d_in[9];
    const float* bm1   = (const float*)d_in[10];
    const float* w2    = (const float*)d_in[11];
    const float* bm2   = (const float*)d_in[12];
    float* out = (float*)d_out;

    float *h, *qkv, *o, *attn, *m, *wq, *wp, *w1t, *w2t;
    cudaGetSymbolAddress((void**)&h,    g_h);
    cudaGetSymbolAddress((void**)&qkv,  g_qkv);
    cudaGetSymbolAddress((void**)&o,    g_o);
    cudaGetSymbolAddress((void**)&attn, g_attn);
    cudaGetSymbolAddress((void**)&m,    g_m);
    cudaGetSymbolAddress((void**)&wq,   g_wq);
    cudaGetSymbolAddress((void**)&wp,   g_wp);
    cudaGetSymbolAddress((void**)&w1t,  g_w1);
    cudaGetSymbolAddress((void**)&w2t,  g_w2);

    cudaFuncSetAttribute((const void*)attn_kernel,
                         cudaFuncAttributeMaxDynamicSharedMemorySize, ATTN_SMEM_BYTES);
    cudaFuncSetAttribute((const void*)gemm_tf32<0>,
                         cudaFuncAttributeMaxDynamicSharedMemorySize, GEMM_DSM);
    cudaFuncSetAttribute((const void*)gemm_tf32<1>,
                         cudaFuncAttributeMaxDynamicSharedMemorySize, GEMM_DSM);
    cudaFuncSetAttribute((const void*)gemm_tf32<2>,
                         cudaFuncAttributeMaxDynamicSharedMemorySize, GEMM_DSM);

    dim3 wblk(32, 8);
    wconv_kernel<<<dim3(QKVDIM / 32, CDIM / 32), wblk>>>(wqkv, wq, CDIM, QKVDIM);
    wconv_kernel<<<dim3(CDIM / 32, CDIM / 32),   wblk>>>(wproj, wp, CDIM, CDIM);
    wconv_kernel<<<dim3(MLPDIM / 32, CDIM / 32), wblk>>>(w1, w1t, CDIM, MLPDIM);
    wconv_kernel<<<dim3(CDIM / 32, MLPDIM / 32), wblk>>>(w2, w2t, MLPDIM, CDIM);

    const int LN_BLOCKS = TOKENS / 8;
    const int MT = TOKENS / 128;   // 784

    // 1. window-partition gather + LN1 -> h (tf32)
    ln_kernel<<<LN_BLOCKS, 256>>>(x, g1, b1, h, 1);

    // 2. qkv = h @ wqkv + bqkv (fp32)
    gemm_tf32<0><<<dim3(QKVDIM / 128, MT), 256, GEMM_DSM>>>(
        h, wq, bqkv, nullptr, qkv, QKVDIM, CDIM);

    // 3. windowed attention -> o (tf32)
    attn_kernel<<<NWINHEAD, 128, ATTN_SMEM_BYTES>>>(qkv, o);

    // 4. attn = o @ wproj + bproj (fp32)
    gemm_tf32<0><<<dim3(CDIM / 128, MT), 256, GEMM_DSM>>>(
        o, wp, bproj, nullptr, attn, CDIM, CDIM);

    // 5. LN2 -> h (tf32)
    ln_kernel<<<LN_BLOCKS, 256>>>(attn, g2, b2, h, 0);

    // 6. m = gelu(h @ w1 + bm1) (tf32)
    gemm_tf32<1><<<dim3(MLPDIM / 128, MT), 256, GEMM_DSM>>>(
        h, w1t, bm1, nullptr, m, MLPDIM, CDIM);

    // 7. out[w2o(r)] = attn[r] + m[r] @ w2 + bm2
    gemm_tf32<2><<<dim3(CDIM / 128, MT), 256, GEMM_DSM>>>(
        m, w2t, bm2, attn, out, CDIM, MLPDIM);
}

// round 13
// speedup vs baseline: 1.2621x; 1.0396x over previous
#include <cuda_runtime.h>
#include <cstdint>

// ---------------------------------------------------------------------------
// Problem constants
// ---------------------------------------------------------------------------
#define TOKENS   100352          // 1024 windows * 98
#define CDIM     512
#define QKVDIM   1536
#define MLPDIM   2048
#define NWINHEAD 16384

// ---------------------------------------------------------------------------
// Scratch (static device arrays). GEMM A-operands / weights are tf32-rounded
// fp32 with K-pair-interleaved layout (kperm); N-side tensors are semantic.
// ---------------------------------------------------------------------------
__device__ __align__(16) float g_h   [(size_t)TOKENS * CDIM];    // LN out (tf32, kperm)
__device__ __align__(16) float g_qkv [(size_t)TOKENS * QKVDIM];  // fp32 semantic
__device__ __align__(16) float g_o   [(size_t)TOKENS * CDIM];    // attn out (tf32, kperm)
__device__ __align__(16) float g_attn[(size_t)TOKENS * CDIM];    // proj out fp32 semantic
__device__ __align__(16) float g_m   [(size_t)TOKENS * MLPDIM];  // gelu out (tf32, kperm)
__device__ __align__(16) float g_wq  [QKVDIM * CDIM];            // [N][K] tf32 kperm
__device__ __align__(16) float g_wp  [CDIM * CDIM];
__device__ __align__(16) float g_w1  [MLPDIM * CDIM];
__device__ __align__(16) float g_w2  [CDIM * MLPDIM];

// ---------------------------------------------------------------------------
// helpers
// ---------------------------------------------------------------------------
__device__ __forceinline__ int w2o(int m) {
    int win = m / 98;
    int n   = m - win * 98;
    int b   = win >> 9;
    int r   = win & 511;
    int wd  = r >> 6;
    int wh  = (r >> 3) & 7;
    int ww  = r & 7;
    int dw  = n / 49;
    int rem = n - dw * 49;
    int hw  = rem / 7;
    int wl  = rem - hw * 7;
    return (((b * 16 + wd * 2 + dw) * 56) + wh * 7 + hw) * 56 + ww * 7 + wl;
}

// K-pair interleave: within each group of 8, order [0,4,1,5,2,6,3,7].
// Thread qc then reads originals (qc, qc+4) as one adjacent float2.
__device__ __forceinline__ int kperm(int k) {
    return (k & ~7) | ((k & 3) << 1) | ((k >> 2) & 1);
}

__device__ __forceinline__ float to_tf32(float x) {
    unsigned u;
    asm("cvt.rna.tf32.f32 %0, %1;" : "=r"(u) : "f"(x));
    return __uint_as_float(u);
}

__device__ __forceinline__ float gelu_tanh(float x) {
    float u = 0.7978845608028654f * (x + 0.044715f * x * x * x);
    return 0.5f * x * (1.f + tanhf(u));
}

__device__ __forceinline__ void cpasync16(unsigned dst, const void* src) {
    asm volatile("cp.async.cg.shared.global [%0], [%1], 16;" :: "r"(dst), "l"(src));
}

__device__ __forceinline__ void mma8(float c[4], const float a[4], const float b[2]) {
    asm volatile(
        "mma.sync.aligned.m16n8k8.row.col.f32.tf32.tf32.f32 "
        "{%0,%1,%2,%3},{%4,%5,%6,%7},{%8,%9},{%0,%1,%2,%3};"
        : "+f"(c[0]), "+f"(c[1]), "+f"(c[2]), "+f"(c[3])
        : "r"(__float_as_uint(a[0])), "r"(__float_as_uint(a[1])),
          "r"(__float_as_uint(a[2])), "r"(__float_as_uint(a[3])),
          "r"(__float_as_uint(b[0])), "r"(__float_as_uint(b[1])));
}

// ---------------------------------------------------------------------------
// Weight convert + transpose: w[K][N] fp32 -> [N][kperm(K)] tf32
// ---------------------------------------------------------------------------
__global__ void wconv_kernel(const float* __restrict__ w, float* __restrict__ wt,
                             int K, int N)
{
    __shared__ float tile[32][33];
    int n0 = blockIdx.x * 32, k0 = blockIdx.y * 32;
    int tx = threadIdx.x, ty = threadIdx.y;
#pragma unroll
    for (int r = 0; r < 4; ++r)
        tile[ty + 8 * r][tx] = w[(size_t)(k0 + ty + 8 * r) * N + n0 + tx];
    __syncthreads();
#pragma unroll
    for (int r = 0; r < 4; ++r) {
        int n = n0 + ty + 8 * r, k = k0 + tx;
        wt[(size_t)n * K + kperm(k)] = to_tf32(tile[tx][ty + 8 * r]);
    }
}

// ---------------------------------------------------------------------------
// LayerNorm -> tf32 (kperm layout)
// ---------------------------------------------------------------------------
__global__ void ln_kernel(const float* __restrict__ x, const float* __restrict__ g,
                          const float* __restrict__ b, float* __restrict__ o,
                          int gather)
{
    int row  = blockIdx.x * 8 + (threadIdx.x >> 5);
    int lane = threadIdx.x & 31;
    if (row >= TOKENS) return;
    int src = gather ? w2o(row) : row;
    const float* xr = x + (size_t)src * CDIM;

    float v[16], s = 0.f, ss = 0.f;
#pragma unroll
    for (int k = 0; k < 16; ++k) {
        float a = xr[lane + 32 * k];
        v[k] = a; s += a; ss += a * a;
    }
#pragma unroll
    for (int off = 16; off; off >>= 1) {
        s  += __shfl_xor_sync(0xffffffffu, s,  off);
        ss += __shfl_xor_sync(0xffffffffu, ss, off);
    }
    float mu   = s * (1.f / 512.f);
    float rstd = rsqrtf(ss * (1.f / 512.f) - mu * mu + 1e-5f);

    size_t ro = (size_t)row * CDIM;
#pragma unroll
    for (int k = 0; k < 16; ++k) {
        int c = lane + 32 * k;
        o[ro + kperm(c)] = to_tf32((v[k] - mu) * rstd * g[c] + b[c]);
    }
}

// ---------------------------------------------------------------------------
// TF32 single-pass GEMM v6:
//   A: [M][kperm(K)] tf32    B: [N][kperm(K)] tf32
// 128x128 tile, BK=32, 2-stage cp.async ring, 256 thr, warps 2x4, wt 64x32.
// Stage (40KB): A[128][40] fp32 | B[128][40] fp32. PADF=40 -> row stride is
// 8 banks, so LDS.64 fragment loads are conflict-free (phase lanes qr0..3
// occupy disjoint bank octets). kperm makes each fragment pair one float2:
// 12 LDS.64 + 16 MMA per k8 (was 24 LDS.32 + 16 MMA).
// ---------------------------------------------------------------------------
#define PADF     40
#define TILEB    (128 * PADF * 4)     // 20480 B
#define OFF_B    TILEB
#define STGB     (2 * TILEB)          // 40960 B
#define GEMM_DSM (2 * STGB)           // 81920 B

// A/B tiles: 1024 16B chunks each; thread t loads 4 of each (coalesced).
__device__ __forceinline__ void load_stage(unsigned sb,
    const float* __restrict__ A, const float* __restrict__ B,
    int K, int bm, int bn, int kt, int t)
{
#pragma unroll
    for (int i = 0; i < 4; ++i) {
        int ch = t + 256 * i;
        int row = ch >> 3, c = ch & 7;
        unsigned so = (unsigned)(row * (PADF * 4) + c * 16);
        cpasync16(sb + so,         A + (size_t)(bm + row) * K + kt * 32 + c * 4);
        cpasync16(sb + OFF_B + so, B + (size_t)(bn + row) * K + kt * 32 + c * 4);
    }
}

// one k8 step (s = 0..3); fragment pairs are adjacent float2 thanks to kperm
__device__ __forceinline__ void compute_k8(const float* sA, const float* sB, int s,
                                           int wm, int wn, int lane, float c[4][4][4])
{
    int qr = lane >> 2;      // 0..7
    int qc = lane & 3;       // 0..3
    float a[4][4];
#pragma unroll
    for (int i = 0; i < 4; ++i) {
        int base = (wm * 64 + i * 16 + qr) * PADF + s * 8 + 2 * qc;
        float2 p0 = *(const float2*)(sA + base);
        float2 p1 = *(const float2*)(sA + base + 8 * PADF);
        a[i][0] = p0.x; a[i][2] = p0.y;
        a[i][1] = p1.x; a[i][3] = p1.y;
    }
    float b[4][2];
#pragma unroll
    for (int j = 0; j < 4; ++j) {
        int base = (wn * 32 + j * 8 + qr) * PADF + s * 8 + 2 * qc;
        float2 p = *(const float2*)(sB + base);
        b[j][0] = p.x; b[j][1] = p.y;
    }
#pragma unroll
    for (int i = 0; i < 4; ++i)
#pragma unroll
        for (int j = 0; j < 4; ++j)
            mma8(c[i][j], a[i], b[j]);
}

// EPI: 0 = +bias -> fp32 semantic ; 1 = +bias,gelu -> tf32 kperm ;
// EPI: 2 = +bias+res, w2o scatter -> fp32 semantic
template <int EPI>
__global__ void __launch_bounds__(256, 2)
gemm_tf32(const float* __restrict__ A, const float* __restrict__ B,
          const float* __restrict__ bias, const float* __restrict__ res,
          float* __restrict__ C, int N, int K)
{
    extern __shared__ char sm_raw[];
    unsigned sb = (unsigned)__cvta_generic_to_shared(sm_raw);

    int t = threadIdx.x;
    int warp = t >> 5, lane = t & 31;
    int wm = warp >> 2, wn = warp & 3;
    int bm = blockIdx.y * 128, bn = blockIdx.x * 128;

    float c[4][4][4];
#pragma unroll
    for (int i = 0; i < 4; ++i)
#pragma unroll
        for (int j = 0; j < 4; ++j)
#pragma unroll
            for (int k = 0; k < 4; ++k) c[i][j][k] = 0.f;

    int KT = K >> 5;                     // BK = 32
    load_stage(sb,        A, B, K, bm, bn, 0, t);
    asm volatile("cp.async.commit_group;" ::: "memory");
    load_stage(sb + STGB, A, B, K, bm, bn, 1, t);
    asm volatile("cp.async.commit_group;" ::: "memory");

    for (int kt = 0; kt < KT; ++kt) {
        if (kt + 1 < KT) asm volatile("cp.async.wait_group 1;" ::: "memory");
        else             asm volatile("cp.async.wait_group 0;" ::: "memory");
        __syncthreads();
        const float* sA = (const float*)(sm_raw + (size_t)(kt & 1) * STGB);
        const float* sB = sA + TILEB / 4;
        compute_k8(sA, sB, 0, wm, wn, lane, c);
        compute_k8(sA, sB, 1, wm, wn, lane, c);
        compute_k8(sA, sB, 2, wm, wn, lane, c);
        compute_k8(sA, sB, 3, wm, wn, lane, c);
        if (kt + 2 < KT) {
            __syncthreads();            // all warps done with this buffer
            load_stage(sb + (unsigned)(kt & 1) * STGB, A, B, K, bm, bn, kt + 2, t);
            asm volatile("cp.async.commit_group;" ::: "memory");
        }
    }

    // epilogue (C frag: rows r0,r0+8 ; cols col,col+1)
#pragma unroll
    for (int i = 0; i < 4; ++i) {
        int r0 = bm + wm * 64 + i * 16 + (lane >> 2);
        int rows[2] = { r0, r0 + 8 };
        int dst[2];
        if (EPI == 2) { dst[0] = w2o(rows[0]); dst[1] = w2o(rows[1]); }
#pragma unroll
        for (int j = 0; j < 4; ++j) {
            int col = bn + wn * 32 + j * 8 + ((lane & 3) << 1);
            float bv0 = bias[col], bv1 = bias[col + 1];
#pragma unroll
            for (int rr = 0; rr < 2; ++rr) {
                float v0 = c[i][j][rr * 2 + 0] + bv0;
                float v1 = c[i][j][rr * 2 + 1] + bv1;
                if (EPI == 0) {
                    size_t oo = (size_t)rows[rr] * (size_t)N + col;
                    C[oo] = v0; C[oo + 1] = v1;
                } else if (EPI == 1) {
                    size_t rb = (size_t)rows[rr] * (size_t)N;
                    C[rb + kperm(col)]     = to_tf32(gelu_tanh(v0));
                    C[rb + kperm(col + 1)] = to_tf32(gelu_tanh(v1));
                } else {
                    size_t ro = (size_t)rows[rr] * CDIM + col;
                    v0 += res[ro]; v1 += res[ro + 1];
                    size_t oo = (size_t)dst[rr] * CDIM + col;
                    C[oo] = v0; C[oo + 1] = v1;
                }
            }
        }
    }
}

// ---------------------------------------------------------------------------
// Windowed attention: one CTA per (window, head). fp32 SIMT. Out tf32+kperm.
// ---------------------------------------------------------------------------
#define SQ_OFF  0
#define SK_OFF  3136
#define SVT_OFF (3136 + 3528)
#define SP_OFF  (SVT_OFF + 3200)
#define ATTN_SMEM_BYTES ((SP_OFF + 9800) * 4)

__global__ void __launch_bounds__(128)
attn_kernel(const float* __restrict__ qkv, float* __restrict__ o)
{
    extern __shared__ float sm[];
    float* sQ  = sm + SQ_OFF;
    float* sK  = sm + SK_OFF;
    float* sVt = sm + SVT_OFF;
    float* sP  = sm + SP_OFF;

    int win  = blockIdx.x >> 4;
    int head = blockIdx.x & 15;
    int t = threadIdx.x, warp = t >> 5, lane = t & 31;

    if (t < 64) sVt[(t >> 1) * 100 + 98 + (t & 1)] = 0.f;

    const float scale = 0.17677669529663687f;
    size_t base = (size_t)win * 98 * QKVDIM + (size_t)head * 32;
    for (int idx = t; idx < 98 * 32; idx += 128) {
        int n = idx >> 5, hd = idx & 31;
        const float* p = qkv + base + (size_t)n * QKVDIM + hd;
        sQ[n * 32 + hd]   = p[0] * scale;
        sK[n * 36 + hd]   = p[512];
        sVt[hd * 100 + n] = p[1024];
    }
    __syncthreads();

    for (int i = warp; i < 98; i += 4) {
        float4 q4[8];
        const float4* qrow = (const float4*)(sQ + i * 32);
#pragma unroll
        for (int cc = 0; cc < 8; ++cc) q4[cc] = qrow[cc];

        float sv[4];
        float mx = -1e30f;
#pragma unroll
        for (int jj = 0; jj < 4; ++jj) {
            int j = lane + jj * 32;
            float a = -1e30f;
            if (j < 98) {
                const float4* krow = (const float4*)(sK + j * 36);
                float acc = 0.f;
#pragma unroll
                for (int cc = 0; cc < 8; ++cc) {
                    float4 k4 = krow[cc];
                    acc += q4[cc].x * k4.x + q4[cc].y * k4.y
                         + q4[cc].z * k4.z + q4[cc].w * k4.w;
                }
                a = acc;
            }
            sv[jj] = a;
            mx = fmaxf(mx, a);
        }
#pragma unroll
        for (int off = 16; off; off >>= 1)
            mx = fmaxf(mx, __shfl_xor_sync(0xffffffffu, mx, off));
        float sum = 0.f;
#pragma unroll
        for (int jj = 0; jj < 4; ++jj) {
            int j = lane + jj * 32;
            float e = (j < 98) ? __expf(sv[jj] - mx) : 0.f;
            sv[jj] = e; sum += e;
        }
#pragma unroll
        for (int off = 16; off; off >>= 1)
            sum += __shfl_xor_sync(0xffffffffu, sum, off);
        float inv = 1.f / sum;
#pragma unroll
        for (int jj = 0; jj < 4; ++jj) {
            int j = lane + jj * 32;
            if (j < 98) sP[i * 100 + j] = sv[jj] * inv;
        }
        if (lane < 2) sP[i * 100 + 98 + lane] = 0.f;
    }
    __syncthreads();

    // output column head*32+lane, stored at kperm position (proj GEMM A-layout)
    size_t obase = (size_t)win * 98 * CDIM + (size_t)kperm(head * 32 + lane);
    const float4* vrow = (const float4*)(sVt + lane * 100);
    for (int i = warp; i < 98; i += 4) {
        const float4* prow = (const float4*)(sP + i * 100);
        float acc = 0.f;
#pragma unroll
        for (int cc = 0; cc < 25; ++cc) {
            float4 p4 = prow[cc];
            float4 v4 = vrow[cc];
            acc += p4.x * v4.x + p4.y * v4.y + p4.z * v4.z + p4.w * v4.w;
        }
        o[obase + (size_t)i * CDIM] = to_tf32(acc);
    }
}

// ---------------------------------------------------------------------------
// launch
// ---------------------------------------------------------------------------
extern "C" void kernel_launch(void* const* d_in, const int* in_sizes, int n_in,
                              void* d_out, int out_size)
{
    (void)in_sizes; (void)n_in; (void)out_size;

    const float* x     = (const float*)d_in[0];
    const float* g1    = (const float*)d_in[1];
    const float* b1    = (const float*)d_in[2];
    const float* wqkv  = (const float*)d_in[3];
    const float* bqkv  = (const float*)d_in[4];
    const float* wproj = (const float*)d_in[5];
    const float* bproj = (const float*)d_in[6];
    const float* g2    = (const float*)d_in[7];
    const float* b2    = (const float*)d_in[8];
    const float* w1    = (const float*)d_in[9];
    const float* bm1   = (const float*)d_in[10];
    const float* w2    = (const float*)d_in[11];
    const float* bm2   = (const float*)d_in[12];
    float* out = (float*)d_out;

    float *h, *qkv, *o, *attn, *m, *wq, *wp, *w1t, *w2t;
    cudaGetSymbolAddress((void**)&h,    g_h);
    cudaGetSymbolAddress((void**)&qkv,  g_qkv);
    cudaGetSymbolAddress((void**)&o,    g_o);
    cudaGetSymbolAddress((void**)&attn, g_attn);
    cudaGetSymbolAddress((void**)&m,    g_m);
    cudaGetSymbolAddress((void**)&wq,   g_wq);
    cudaGetSymbolAddress((void**)&wp,   g_wp);
    cudaGetSymbolAddress((void**)&w1t,  g_w1);
    cudaGetSymbolAddress((void**)&w2t,  g_w2);

    cudaFuncSetAttribute((const void*)attn_kernel,
                         cudaFuncAttributeMaxDynamicSharedMemorySize, ATTN_SMEM_BYTES);
    cudaFuncSetAttribute((const void*)gemm_tf32<0>,
                         cudaFuncAttributeMaxDynamicSharedMemorySize, GEMM_DSM);
    cudaFuncSetAttribute((const void*)gemm_tf32<1>,
                         cudaFuncAttributeMaxDynamicSharedMemorySize, GEMM_DSM);
    cudaFuncSetAttribute((const void*)gemm_tf32<2>,
                         cudaFuncAttributeMaxDynamicSharedMemorySize, GEMM_DSM);

    dim3 wblk(32, 8);
    wconv_kernel<<<dim3(QKVDIM / 32, CDIM / 32), wblk>>>(wqkv, wq, CDIM, QKVDIM);
    wconv_kernel<<<dim3(CDIM / 32, CDIM / 32),   wblk>>>(wproj, wp, CDIM, CDIM);
    wconv_kernel<<<dim3(MLPDIM / 32, CDIM / 32), wblk>>>(w1, w1t, CDIM, MLPDIM);
    wconv_kernel<<<dim3(CDIM / 32, MLPDIM / 32), wblk>>>(w2, w2t, MLPDIM, CDIM);

    const int LN_BLOCKS = TOKENS / 8;
    const int MT = TOKENS / 128;   // 784

    // 1. window-partition gather + LN1 -> h (tf32, kperm)
    ln_kernel<<<LN_BLOCKS, 256>>>(x, g1, b1, h, 1);

    // 2. qkv = h @ wqkv + bqkv (fp32 semantic)
    gemm_tf32<0><<<dim3(QKVDIM / 128, MT), 256, GEMM_DSM>>>(
        h, wq, bqkv, nullptr, qkv, QKVDIM, CDIM);

    // 3. windowed attention -> o (tf32, kperm)
    attn_kernel<<<NWINHEAD, 128, ATTN_SMEM_BYTES>>>(qkv, o);

    // 4. attn = o @ wproj + bproj (fp32 semantic)
    gemm_tf32<0><<<dim3(CDIM / 128, MT), 256, GEMM_DSM>>>(
        o, wp, bproj, nullptr, attn, CDIM, CDIM);

    // 5. LN2 -> h (tf32, kperm)
    ln_kernel<<<LN_BLOCKS, 256>>>(attn, g2, b2, h, 0);

    // 6. m = gelu(h @ w1 + bm1) (tf32, kperm over MLP dim)
    gemm_tf32<1><<<dim3(MLPDIM / 128, MT), 256, GEMM_DSM>>>(
        h, w1t, bm1, nullptr, m, MLPDIM, CDIM);

    // 7. out[w2o(r)] = attn[r] + m[r] @ w2 + bm2
    gemm_tf32<2><<<dim3(CDIM / 128, MT), 256, GEMM_DSM>>>(
        m, w2t, bm2, attn, out, CDIM, MLPDIM);
}

// round 14
// speedup vs baseline: 1.6487x; 1.3063x over previous
#include <cuda_runtime.h>
#include <cuda_fp16.h>
#include <cstdint>

// ---------------------------------------------------------------------------
// Problem constants
// ---------------------------------------------------------------------------
#define TOKENS   100352          // 1024 windows * 98
#define CDIM     512
#define QKVDIM   1536
#define MLPDIM   2048
#define NWINHEAD 16384

typedef unsigned short u16;

// ---------------------------------------------------------------------------
// Scratch (static device arrays). GEMM operands fp16 (same 10-bit mantissa as
// tf32 -> same quantization error), semantic [*][K] layout for ldmatrix.
// ---------------------------------------------------------------------------
__device__ __align__(16) u16   g_h   [(size_t)TOKENS * CDIM];    // LN out fp16
__device__ __align__(16) float g_qkv [(size_t)TOKENS * QKVDIM];  // fp32
__device__ __align__(16) u16   g_o   [(size_t)TOKENS * CDIM];    // attn out fp16
__device__ __align__(16) float g_attn[(size_t)TOKENS * CDIM];    // proj out fp32
__device__ __align__(16) u16   g_m   [(size_t)TOKENS * MLPDIM];  // gelu out fp16
__device__ __align__(16) u16   g_wq  [QKVDIM * CDIM];            // [N][K] fp16
__device__ __align__(16) u16   g_wp  [CDIM * CDIM];
__device__ __align__(16) u16   g_w1  [MLPDIM * CDIM];
__device__ __align__(16) u16   g_w2  [CDIM * MLPDIM];

// ---------------------------------------------------------------------------
// helpers
// ---------------------------------------------------------------------------
__device__ __forceinline__ int w2o(int m) {
    int win = m / 98;
    int n   = m - win * 98;
    int b   = win >> 9;
    int r   = win & 511;
    int wd  = r >> 6;
    int wh  = (r >> 3) & 7;
    int ww  = r & 7;
    int dw  = n / 49;
    int rem = n - dw * 49;
    int hw  = rem / 7;
    int wl  = rem - hw * 7;
    return (((b * 16 + wd * 2 + dw) * 56) + wh * 7 + hw) * 56 + ww * 7 + wl;
}

__device__ __forceinline__ u16 f2h(float x) {
    __half h = __float2half_rn(x);
    return *reinterpret_cast<u16*>(&h);
}

__device__ __forceinline__ float gelu_tanh(float x) {
    float u = 0.7978845608028654f * (x + 0.044715f * x * x * x);
    return 0.5f * x * (1.f + tanhf(u));
}

__device__ __forceinline__ void cpasync16(unsigned dst, const void* src) {
    asm volatile("cp.async.cg.shared.global [%0], [%1], 16;" :: "r"(dst), "l"(src));
}

__device__ __forceinline__ void ldsm4(unsigned r[4], unsigned addr) {
    asm volatile("ldmatrix.sync.aligned.m8n8.x4.shared.b16 {%0,%1,%2,%3}, [%4];"
                 : "=r"(r[0]), "=r"(r[1]), "=r"(r[2]), "=r"(r[3]) : "r"(addr));
}

__device__ __forceinline__ void mma16(float c[4], const unsigned a[4], const unsigned b[2]) {
    asm volatile(
        "mma.sync.aligned.m16n8k16.row.col.f32.f16.f16.f32 "
        "{%0,%1,%2,%3},{%4,%5,%6,%7},{%8,%9},{%0,%1,%2,%3};"
        : "+f"(c[0]), "+f"(c[1]), "+f"(c[2]), "+f"(c[3])
        : "r"(a[0]), "r"(a[1]), "r"(a[2]), "r"(a[3]), "r"(b[0]), "r"(b[1]));
}

// ---------------------------------------------------------------------------
// Weight convert + transpose: w[K][N] fp32 -> [N][K] fp16
// ---------------------------------------------------------------------------
__global__ void wconv_kernel(const float* __restrict__ w, u16* __restrict__ wt,
                             int K, int N)
{
    __shared__ float tile[32][33];
    int n0 = blockIdx.x * 32, k0 = blockIdx.y * 32;
    int tx = threadIdx.x, ty = threadIdx.y;
#pragma unroll
    for (int r = 0; r < 4; ++r)
        tile[ty + 8 * r][tx] = w[(size_t)(k0 + ty + 8 * r) * N + n0 + tx];
    __syncthreads();
#pragma unroll
    for (int r = 0; r < 4; ++r) {
        int n = n0 + ty + 8 * r, k = k0 + tx;
        wt[(size_t)n * K + k] = f2h(tile[tx][ty + 8 * r]);
    }
}

// ---------------------------------------------------------------------------
// LayerNorm -> fp16
// ---------------------------------------------------------------------------
__global__ void ln_kernel(const float* __restrict__ x, const float* __restrict__ g,
                          const float* __restrict__ b, u16* __restrict__ o,
                          int gather)
{
    int row  = blockIdx.x * 8 + (threadIdx.x >> 5);
    int lane = threadIdx.x & 31;
    if (row >= TOKENS) return;
    int src = gather ? w2o(row) : row;
    const float* xr = x + (size_t)src * CDIM;

    float v[16], s = 0.f, ss = 0.f;
#pragma unroll
    for (int k = 0; k < 16; ++k) {
        float a = xr[lane + 32 * k];
        v[k] = a; s += a; ss += a * a;
    }
#pragma unroll
    for (int off = 16; off; off >>= 1) {
        s  += __shfl_xor_sync(0xffffffffu, s,  off);
        ss += __shfl_xor_sync(0xffffffffu, ss, off);
    }
    float mu   = s * (1.f / 512.f);
    float rstd = rsqrtf(ss * (1.f / 512.f) - mu * mu + 1e-5f);

    size_t ro = (size_t)row * CDIM;
#pragma unroll
    for (int k = 0; k < 16; ++k) {
        int c = lane + 32 * k;
        o[ro + c] = f2h((v[k] - mu) * rstd * g[c] + b[c]);
    }
}

// ---------------------------------------------------------------------------
// FP16 single-pass GEMM v7 (R8 skeleton, one MMA term):
//   A: [M][K] fp16    B: [N][K] fp16
// 128x128 tile, BK=32, 3-stage cp.async ring, 256 thr, warps 2x4, wt 64x32.
// Stage (16KB): A[128][32] fp16 | B[128][32] fp16, rows 64B.
// Swizzle: 16B chunk c -> c ^ ((row>>1)&3)  (store & ldmatrix conflict-free,
// validated in R8). Mainloop per k16: 6 LDSM.x4 + 16 MMA (was 56 issue in tf32).
// ---------------------------------------------------------------------------
#define STG16    16384
#define OFF_B    8192
#define GEMM_DSM (3 * STG16)     // 48KB dynamic

__device__ __forceinline__ unsigned swz64(int row, int c) {
    return (unsigned)(row * 64 + ((c ^ ((row >> 1) & 3)) << 4));
}

// A,B: 512 chunks of 16B each; thread t loads 2 of each
__device__ __forceinline__ void load_stage(unsigned sb,
    const u16* __restrict__ A, const u16* __restrict__ B,
    int K, int bm, int bn, int kt, int t)
{
#pragma unroll
    for (int i = 0; i < 2; ++i) {
        int ch = t * 2 + i;
        int row = ch >> 2, c = ch & 3;
        unsigned so = swz64(row, c);
        cpasync16(sb + so,         A + (size_t)(bm + row) * K + kt * 32 + c * 8);
        cpasync16(sb + OFF_B + so, B + (size_t)(bn + row) * K + kt * 32 + c * 8);
    }
}

// one k16 half (kk = 0/1) from a stage — R8 fragment mapping, single term
__device__ __forceinline__ void compute_k16(unsigned base, int kk,
                                            int wm, int wn, int lane, float c[4][4][4])
{
    int mat  = lane >> 3;
    int rsub = lane & 7;
    int aRow = (mat & 1) * 8 + rsub;  int aCh = kk * 2 + (mat >> 1);
    int bRow = (mat >> 1) * 8 + rsub; int bCh = kk * 2 + (mat & 1);

    unsigned A[4][4], B[2][4];
#pragma unroll
    for (int i = 0; i < 4; ++i)
        ldsm4(A[i], base + swz64(wm * 64 + i * 16 + aRow, aCh));
#pragma unroll
    for (int g = 0; g < 2; ++g)
        ldsm4(B[g], base + OFF_B + swz64(wn * 32 + g * 16 + bRow, bCh));
#pragma unroll
    for (int i = 0; i < 4; ++i)
#pragma unroll
        for (int j = 0; j < 4; ++j)
            mma16(c[i][j], A[i], &B[j >> 1][(j & 1) * 2]);
}

// EPI: 0 = +bias -> fp32 ; 1 = +bias,gelu -> fp16 ; 2 = +bias+res, w2o scatter
template <int EPI>
__global__ void __launch_bounds__(256, 2)
gemm_fp16(const u16* __restrict__ A, const u16* __restrict__ B,
          const float* __restrict__ bias, const float* __restrict__ res,
          float* __restrict__ Cf, u16* __restrict__ Ch,
          int N, int K)
{
    extern __shared__ char sm_raw[];
    unsigned sb = (unsigned)__cvta_generic_to_shared(sm_raw);

    int t = threadIdx.x;
    int warp = t >> 5, lane = t & 31;
    int wm = warp >> 2, wn = warp & 3;
    int bm = blockIdx.y * 128, bn = blockIdx.x * 128;

    float c[4][4][4];
#pragma unroll
    for (int i = 0; i < 4; ++i)
#pragma unroll
        for (int j = 0; j < 4; ++j)
#pragma unroll
            for (int k = 0; k < 4; ++k) c[i][j][k] = 0.f;

    int KT = K >> 5;                     // BK = 32
    load_stage(sb,         A, B, K, bm, bn, 0, t);
    asm volatile("cp.async.commit_group;" ::: "memory");
    load_stage(sb + STG16, A, B, K, bm, bn, 1, t);
    asm volatile("cp.async.commit_group;" ::: "memory");

    for (int kt = 0; kt < KT; ++kt) {
        if (kt + 1 < KT) asm volatile("cp.async.wait_group 1;" ::: "memory");
        else             asm volatile("cp.async.wait_group 0;" ::: "memory");
        __syncthreads();
        if (kt + 2 < KT) {
            load_stage(sb + (unsigned)((kt + 2) % 3) * STG16,
                       A, B, K, bm, bn, kt + 2, t);
            asm volatile("cp.async.commit_group;" ::: "memory");
        }
        unsigned base = sb + (unsigned)(kt % 3) * STG16;
        compute_k16(base, 0, wm, wn, lane, c);
        compute_k16(base, 1, wm, wn, lane, c);
    }

    // epilogue (C frag: rows r0,r0+8 ; cols col,col+1)
#pragma unroll
    for (int i = 0; i < 4; ++i) {
        int r0 = bm + wm * 64 + i * 16 + (lane >> 2);
        int rows[2] = { r0, r0 + 8 };
        int dst[2];
        if (EPI == 2) { dst[0] = w2o(rows[0]); dst[1] = w2o(rows[1]); }
#pragma unroll
        for (int j = 0; j < 4; ++j) {
            int col = bn + wn * 32 + j * 8 + ((lane & 3) << 1);
            float bv0 = bias[col], bv1 = bias[col + 1];
#pragma unroll
            for (int rr = 0; rr < 2; ++rr) {
                float v0 = c[i][j][rr * 2 + 0] + bv0;
                float v1 = c[i][j][rr * 2 + 1] + bv1;
                if (EPI == 0) {
                    size_t oo = (size_t)rows[rr] * (size_t)N + col;
                    Cf[oo] = v0; Cf[oo + 1] = v1;
                } else if (EPI == 1) {
                    size_t oo = (size_t)rows[rr] * (size_t)N + col;
                    Ch[oo]     = f2h(gelu_tanh(v0));
                    Ch[oo + 1] = f2h(gelu_tanh(v1));
                } else {
                    size_t ro = (size_t)rows[rr] * CDIM + col;
                    v0 += res[ro]; v1 += res[ro + 1];
                    size_t oo = (size_t)dst[rr] * CDIM + col;
                    Cf[oo] = v0; Cf[oo + 1] = v1;
                }
            }
        }
    }
}

// ---------------------------------------------------------------------------
// Windowed attention: one CTA per (window, head). fp32 SIMT. Out fp16.
// ---------------------------------------------------------------------------
#define SQ_OFF  0
#define SK_OFF  3136
#define SVT_OFF (3136 + 3528)
#define SP_OFF  (SVT_OFF + 3200)
#define ATTN_SMEM_BYTES ((SP_OFF + 9800) * 4)

__global__ void __launch_bounds__(128)
attn_kernel(const float* __restrict__ qkv, u16* __restrict__ o)
{
    extern __shared__ float sm[];
    float* sQ  = sm + SQ_OFF;
    float* sK  = sm + SK_OFF;
    float* sVt = sm + SVT_OFF;
    float* sP  = sm + SP_OFF;

    int win  = blockIdx.x >> 4;
    int head = blockIdx.x & 15;
    int t = threadIdx.x, warp = t >> 5, lane = t & 31;

    if (t < 64) sVt[(t >> 1) * 100 + 98 + (t & 1)] = 0.f;

    const float scale = 0.17677669529663687f;
    size_t base = (size_t)win * 98 * QKVDIM + (size_t)head * 32;
    for (int idx = t; idx < 98 * 32; idx += 128) {
        int n = idx >> 5, hd = idx & 31;
        const float* p = qkv + base + (size_t)n * QKVDIM + hd;
        sQ[n * 32 + hd]   = p[0] * scale;
        sK[n * 36 + hd]   = p[512];
        sVt[hd * 100 + n] = p[1024];
    }
    __syncthreads();

    for (int i = warp; i < 98; i += 4) {
        float4 q4[8];
        const float4* qrow = (const float4*)(sQ + i * 32);
#pragma unroll
        for (int cc = 0; cc < 8; ++cc) q4[cc] = qrow[cc];

        float sv[4];
        float mx = -1e30f;
#pragma unroll
        for (int jj = 0; jj < 4; ++jj) {
            int j = lane + jj * 32;
            float a = -1e30f;
            if (j < 98) {
                const float4* krow = (const float4*)(sK + j * 36);
                float acc = 0.f;
#pragma unroll
                for (int cc = 0; cc < 8; ++cc) {
                    float4 k4 = krow[cc];
                    acc += q4[cc].x * k4.x + q4[cc].y * k4.y
                         + q4[cc].z * k4.z + q4[cc].w * k4.w;
                }
                a = acc;
            }
            sv[jj] = a;
            mx = fmaxf(mx, a);
        }
#pragma unroll
        for (int off = 16; off; off >>= 1)
            mx = fmaxf(mx, __shfl_xor_sync(0xffffffffu, mx, off));
        float sum = 0.f;
#pragma unroll
        for (int jj = 0; jj < 4; ++jj) {
            int j = lane + jj * 32;
            float e = (j < 98) ? __expf(sv[jj] - mx) : 0.f;
            sv[jj] = e; sum += e;
        }
#pragma unroll
        for (int off = 16; off; off >>= 1)
            sum += __shfl_xor_sync(0xffffffffu, sum, off);
        float inv = 1.f / sum;
#pragma unroll
        for (int jj = 0; jj < 4; ++jj) {
            int j = lane + jj * 32;
            if (j < 98) sP[i * 100 + j] = sv[jj] * inv;
        }
        if (lane < 2) sP[i * 100 + 98 + lane] = 0.f;
    }
    __syncthreads();

    size_t obase = (size_t)win * 98 * CDIM + (size_t)head * 32 + lane;
    const float4* vrow = (const float4*)(sVt + lane * 100);
    for (int i = warp; i < 98; i += 4) {
        const float4* prow = (const float4*)(sP + i * 100);
        float acc = 0.f;
#pragma unroll
        for (int cc = 0; cc < 25; ++cc) {
            float4 p4 = prow[cc];
            float4 v4 = vrow[cc];
            acc += p4.x * v4.x + p4.y * v4.y + p4.z * v4.z + p4.w * v4.w;
        }
        o[obase + (size_t)i * CDIM] = f2h(acc);
    }
}

// ---------------------------------------------------------------------------
// launch
// ---------------------------------------------------------------------------
extern "C" void kernel_launch(void* const* d_in, const int* in_sizes, int n_in,
                              void* d_out, int out_size)
{
    (void)in_sizes; (void)n_in; (void)out_size;

    const float* x     = (const float*)d_in[0];
    const float* g1    = (const float*)d_in[1];
    const float* b1    = (const float*)d_in[2];
    const float* wqkv  = (const float*)d_in[3];
    const float* bqkv  = (const float*)d_in[4];
    const float* wproj = (const float*)d_in[5];
    const float* bproj = (const float*)d_in[6];
    const float* g2    = (const float*)d_in[7];
    const float* b2    = (const float*)d_in[8];
    const float* w1    = (const float*)d_in[9];
    const float* bm1   = (const float*)d_in[10];
    const float* w2    = (const float*)d_in[11];
    const float* bm2   = (const float*)d_in[12];
    float* out = (float*)d_out;

    u16 *h, *o, *m, *wq, *wp, *w1t, *w2t;
    float *qkv, *attn;
    cudaGetSymbolAddress((void**)&h,    g_h);
    cudaGetSymbolAddress((void**)&qkv,  g_qkv);
    cudaGetSymbolAddress((void**)&o,    g_o);
    cudaGetSymbolAddress((void**)&attn, g_attn);
    cudaGetSymbolAddress((void**)&m,    g_m);
    cudaGetSymbolAddress((void**)&wq,   g_wq);
    cudaGetSymbolAddress((void**)&wp,   g_wp);
    cudaGetSymbolAddress((void**)&w1t,  g_w1);
    cudaGetSymbolAddress((void**)&w2t,  g_w2);

    cudaFuncSetAttribute((const void*)attn_kernel,
                         cudaFuncAttributeMaxDynamicSharedMemorySize, ATTN_SMEM_BYTES);

    dim3 wblk(32, 8);
    wconv_kernel<<<dim3(QKVDIM / 32, CDIM / 32), wblk>>>(wqkv, wq, CDIM, QKVDIM);
    wconv_kernel<<<dim3(CDIM / 32, CDIM / 32),   wblk>>>(wproj, wp, CDIM, CDIM);
    wconv_kernel<<<dim3(MLPDIM / 32, CDIM / 32), wblk>>>(w1, w1t, CDIM, MLPDIM);
    wconv_kernel<<<dim3(CDIM / 32, MLPDIM / 32), wblk>>>(w2, w2t, MLPDIM, CDIM);

    const int LN_BLOCKS = TOKENS / 8;
    const int MT = TOKENS / 128;   // 784

    // 1. window-partition gather + LN1 -> h (fp16)
    ln_kernel<<<LN_BLOCKS, 256>>>(x, g1, b1, h, 1);

    // 2. qkv = h @ wqkv + bqkv (fp32)
    gemm_fp16<0><<<dim3(QKVDIM / 128, MT), 256, GEMM_DSM>>>(
        h, wq, bqkv, nullptr, qkv, nullptr, QKVDIM, CDIM);

    // 3. windowed attention -> o (fp16)
    attn_kernel<<<NWINHEAD, 128, ATTN_SMEM_BYTES>>>(qkv, o);

    // 4. attn = o @ wproj + bproj (fp32)
    gemm_fp16<0><<<dim3(CDIM / 128, MT), 256, GEMM_DSM>>>(
        o, wp, bproj, nullptr, attn, nullptr, CDIM, CDIM);

    // 5. LN2 -> h (fp16)
    ln_kernel<<<LN_BLOCKS, 256>>>(attn, g2, b2, h, 0);

    // 6. m = gelu(h @ w1 + bm1) (fp16)
    gemm_fp16<1><<<dim3(MLPDIM / 128, MT), 256, GEMM_DSM>>>(
        h, w1t, bm1, nullptr, nullptr, m, MLPDIM, CDIM);

    // 7. out[w2o(r)] = attn[r] + m[r] @ w2 + bm2
    gemm_fp16<2><<<dim3(CDIM / 128, MT), 256, GEMM_DSM>>>(
        m, w2t, bm2, attn, out, nullptr, CDIM, MLPDIM);
}

// round 16
// speedup vs baseline: 2.2384x; 1.3577x over previous
#include <cuda_runtime.h>
#include <cuda_fp16.h>
#include <cstdint>

// ---------------------------------------------------------------------------
// Problem constants
// ---------------------------------------------------------------------------
#define TOKENS   100352          // 1024 windows * 98
#define CDIM     512
#define QKVDIM   1536
#define MLPDIM   2048
#define NWINHEAD 16384

typedef unsigned short u16;

// ---------------------------------------------------------------------------
// Scratch
// ---------------------------------------------------------------------------
__device__ __align__(16) u16   g_h   [(size_t)TOKENS * CDIM];    // LN out fp16
__device__ __align__(16) float g_qkv [(size_t)TOKENS * QKVDIM];  // fp32
__device__ __align__(16) u16   g_o   [(size_t)TOKENS * CDIM];    // attn out fp16
__device__ __align__(16) float g_attn[(size_t)TOKENS * CDIM];    // proj out fp32
__device__ __align__(16) u16   g_m   [(size_t)TOKENS * MLPDIM];  // gelu out fp16
__device__ __align__(16) u16   g_wq  [QKVDIM * CDIM];            // [N][K] fp16
__device__ __align__(16) u16   g_wp  [CDIM * CDIM];
__device__ __align__(16) u16   g_w1  [MLPDIM * CDIM];
__device__ __align__(16) u16   g_w2  [CDIM * MLPDIM];

// ---------------------------------------------------------------------------
// helpers
// ---------------------------------------------------------------------------
__device__ __forceinline__ int w2o(int m) {
    int win = m / 98;
    int n   = m - win * 98;
    int b   = win >> 9;
    int r   = win & 511;
    int wd  = r >> 6;
    int wh  = (r >> 3) & 7;
    int ww  = r & 7;
    int dw  = n / 49;
    int rem = n - dw * 49;
    int hw  = rem / 7;
    int wl  = rem - hw * 7;
    return (((b * 16 + wd * 2 + dw) * 56) + wh * 7 + hw) * 56 + ww * 7 + wl;
}

__device__ __forceinline__ u16 f2h(float x) {
    __half h = __float2half_rn(x);
    return *reinterpret_cast<u16*>(&h);
}

__device__ __forceinline__ float gelu_tanh(float x) {
    float u = 0.7978845608028654f * (x + 0.044715f * x * x * x);
    return 0.5f * x * (1.f + tanhf(u));
}

__device__ __forceinline__ void cpasync16(unsigned dst, const void* src) {
    asm volatile("cp.async.cg.shared.global [%0], [%1], 16;" :: "r"(dst), "l"(src));
}

__device__ __forceinline__ void ldsm4(unsigned r[4], unsigned addr) {
    asm volatile("ldmatrix.sync.aligned.m8n8.x4.shared.b16 {%0,%1,%2,%3}, [%4];"
                 : "=r"(r[0]), "=r"(r[1]), "=r"(r[2]), "=r"(r[3]) : "r"(addr));
}

__device__ __forceinline__ void mma16(float c[4], const unsigned a[4], const unsigned b[2]) {
    asm volatile(
        "mma.sync.aligned.m16n8k16.row.col.f32.f16.f16.f32 "
        "{%0,%1,%2,%3},{%4,%5,%6,%7},{%8,%9},{%0,%1,%2,%3};"
        : "+f"(c[0]), "+f"(c[1]), "+f"(c[2]), "+f"(c[3])
        : "r"(a[0]), "r"(a[1]), "r"(a[2]), "r"(a[3]), "r"(b[0]), "r"(b[1]));
}

__device__ __forceinline__ unsigned swz64(int row, int c) {
    return (unsigned)(row * 64 + ((c ^ ((row >> 1) & 3)) << 4));
}

// pack float4 -> 4 fp16 (x in lowest)
__device__ __forceinline__ uint2 f4h(float4 v) {
    unsigned lo, hi;
    asm("cvt.rn.f16x2.f32 %0, %1, %2;" : "=r"(lo) : "f"(v.y), "f"(v.x));
    asm("cvt.rn.f16x2.f32 %0, %1, %2;" : "=r"(hi) : "f"(v.w), "f"(v.z));
    return make_uint2(lo, hi);
}

// ---------------------------------------------------------------------------
// Weight convert + transpose: w[K][N] fp32 -> [N][K] fp16
// ---------------------------------------------------------------------------
__global__ void wconv_kernel(const float* __restrict__ w, u16* __restrict__ wt,
                             int K, int N)
{
    __shared__ float tile[32][33];
    int n0 = blockIdx.x * 32, k0 = blockIdx.y * 32;
    int tx = threadIdx.x, ty = threadIdx.y;
#pragma unroll
    for (int r = 0; r < 4; ++r)
        tile[ty + 8 * r][tx] = w[(size_t)(k0 + ty + 8 * r) * N + n0 + tx];
    __syncthreads();
#pragma unroll
    for (int r = 0; r < 4; ++r) {
        int n = n0 + ty + 8 * r, k = k0 + tx;
        wt[(size_t)n * K + k] = f2h(tile[tx][ty + 8 * r]);
    }
}

// ---------------------------------------------------------------------------
// LayerNorm -> fp16
// ---------------------------------------------------------------------------
__global__ void ln_kernel(const float* __restrict__ x, const float* __restrict__ g,
                          const float* __restrict__ b, u16* __restrict__ o,
                          int gather)
{
    int row  = blockIdx.x * 8 + (threadIdx.x >> 5);
    int lane = threadIdx.x & 31;
    if (row >= TOKENS) return;
    int src = gather ? w2o(row) : row;
    const float* xr = x + (size_t)src * CDIM;

    float v[16], s = 0.f, ss = 0.f;
#pragma unroll
    for (int k = 0; k < 16; ++k) {
        float a = xr[lane + 32 * k];
        v[k] = a; s += a; ss += a * a;
    }
#pragma unroll
    for (int off = 16; off; off >>= 1) {
        s  += __shfl_xor_sync(0xffffffffu, s,  off);
        ss += __shfl_xor_sync(0xffffffffu, ss, off);
    }
    float mu   = s * (1.f / 512.f);
    float rstd = rsqrtf(ss * (1.f / 512.f) - mu * mu + 1e-5f);

    size_t ro = (size_t)row * CDIM;
#pragma unroll
    for (int k = 0; k < 16; ++k) {
        int c = lane + 32 * k;
        o[ro + c] = f2h((v[k] - mu) * rstd * g[c] + b[c]);
    }
}

// ---------------------------------------------------------------------------
// FP16 single-pass GEMM (R14, unchanged — proven at rel_err 6.08e-4):
// 128x128 tile, BK=32, 3-stage cp.async, 256 thr, warps 2x4, wt 64x32.
// ---------------------------------------------------------------------------
#define STG16    16384
#define OFF_B    8192
#define GEMM_DSM (3 * STG16)

__device__ __forceinline__ void load_stage(unsigned sb,
    const u16* __restrict__ A, const u16* __restrict__ B,
    int K, int bm, int bn, int kt, int t)
{
#pragma unroll
    for (int i = 0; i < 2; ++i) {
        int ch = t * 2 + i;
        int row = ch >> 2, c = ch & 3;
        unsigned so = swz64(row, c);
        cpasync16(sb + so,         A + (size_t)(bm + row) * K + kt * 32 + c * 8);
        cpasync16(sb + OFF_B + so, B + (size_t)(bn + row) * K + kt * 32 + c * 8);
    }
}

__device__ __forceinline__ void compute_k16(unsigned base, int kk,
                                            int wm, int wn, int lane, float c[4][4][4])
{
    int mat  = lane >> 3;
    int rsub = lane & 7;
    int aRow = (mat & 1) * 8 + rsub;  int aCh = kk * 2 + (mat >> 1);
    int bRow = (mat >> 1) * 8 + rsub; int bCh = kk * 2 + (mat & 1);

    unsigned A[4][4], B[2][4];
#pragma unroll
    for (int i = 0; i < 4; ++i)
        ldsm4(A[i], base + swz64(wm * 64 + i * 16 + aRow, aCh));
#pragma unroll
    for (int g = 0; g < 2; ++g)
        ldsm4(B[g], base + OFF_B + swz64(wn * 32 + g * 16 + bRow, bCh));
#pragma unroll
    for (int i = 0; i < 4; ++i)
#pragma unroll
        for (int j = 0; j < 4; ++j)
            mma16(c[i][j], A[i], &B[j >> 1][(j & 1) * 2]);
}

// EPI: 0 = +bias -> fp32 ; 1 = +bias,gelu -> fp16 ; 2 = +bias+res, w2o scatter
template <int EPI>
__global__ void __launch_bounds__(256, 2)
gemm_fp16(const u16* __restrict__ A, const u16* __restrict__ B,
          const float* __restrict__ bias, const float* __restrict__ res,
          float* __restrict__ Cf, u16* __restrict__ Ch,
          int N, int K)
{
    extern __shared__ char sm_raw[];
    unsigned sb = (unsigned)__cvta_generic_to_shared(sm_raw);

    int t = threadIdx.x;
    int warp = t >> 5, lane = t & 31;
    int wm = warp >> 2, wn = warp & 3;
    int bm = blockIdx.y * 128, bn = blockIdx.x * 128;

    float c[4][4][4];
#pragma unroll
    for (int i = 0; i < 4; ++i)
#pragma unroll
        for (int j = 0; j < 4; ++j)
#pragma unroll
            for (int k = 0; k < 4; ++k) c[i][j][k] = 0.f;

    int KT = K >> 5;
    load_stage(sb,         A, B, K, bm, bn, 0, t);
    asm volatile("cp.async.commit_group;" ::: "memory");
    load_stage(sb + STG16, A, B, K, bm, bn, 1, t);
    asm volatile("cp.async.commit_group;" ::: "memory");

    for (int kt = 0; kt < KT; ++kt) {
        if (kt + 1 < KT) asm volatile("cp.async.wait_group 1;" ::: "memory");
        else             asm volatile("cp.async.wait_group 0;" ::: "memory");
        __syncthreads();
        if (kt + 2 < KT) {
            load_stage(sb + (unsigned)((kt + 2) % 3) * STG16,
                       A, B, K, bm, bn, kt + 2, t);
            asm volatile("cp.async.commit_group;" ::: "memory");
        }
        unsigned base = sb + (unsigned)(kt % 3) * STG16;
        compute_k16(base, 0, wm, wn, lane, c);
        compute_k16(base, 1, wm, wn, lane, c);
    }

#pragma unroll
    for (int i = 0; i < 4; ++i) {
        int r0 = bm + wm * 64 + i * 16 + (lane >> 2);
        int rows[2] = { r0, r0 + 8 };
        int dst[2];
        if (EPI == 2) { dst[0] = w2o(rows[0]); dst[1] = w2o(rows[1]); }
#pragma unroll
        for (int j = 0; j < 4; ++j) {
            int col = bn + wn * 32 + j * 8 + ((lane & 3) << 1);
            float bv0 = bias[col], bv1 = bias[col + 1];
#pragma unroll
            for (int rr = 0; rr < 2; ++rr) {
                float v0 = c[i][j][rr * 2 + 0] + bv0;
                float v1 = c[i][j][rr * 2 + 1] + bv1;
                if (EPI == 0) {
                    size_t oo = (size_t)rows[rr] * (size_t)N + col;
                    Cf[oo] = v0; Cf[oo + 1] = v1;
                } else if (EPI == 1) {
                    size_t oo = (size_t)rows[rr] * (size_t)N + col;
                    Ch[oo]     = f2h(gelu_tanh(v0));
                    Ch[oo + 1] = f2h(gelu_tanh(v1));
                } else {
                    size_t ro = (size_t)rows[rr] * CDIM + col;
                    v0 += res[ro]; v1 += res[ro + 1];
                    size_t oo = (size_t)dst[rr] * CDIM + col;
                    Cf[oo] = v0; Cf[oo + 1] = v1;
                }
            }
        }
    }
}

// ---------------------------------------------------------------------------
// Tensor-core windowed attention. CTA = (window, head), 128 threads, 4 warps.
// S[112,104] = Q@K^T via m16n8k16 (13 n8 tiles, cols>=98 masked).
// Softmax: max via shfl, exp via ex2.approx.f16x2 (scale*log2e folded),
// row sums via a ones-column appended to V (fp32 from the PV MMA).
// P stays in registers (S C-frag == PV A-frag after f16x2 packing).
// ---------------------------------------------------------------------------
#define VTS 120   // Vt row stride (fp16 elems); 240B rows, conflict-free phases

__global__ void __launch_bounds__(128)
attn_kernel(const float* __restrict__ qkvf, u16* __restrict__ o)
{
    __shared__ __align__(16) u16 sQ[112 * 32];
    __shared__ __align__(16) u16 sK[112 * 32];
    __shared__ __align__(16) u16 sVt[48 * VTS];   // rows 0-31: V^T, row 32: ones

    int win  = blockIdx.x >> 4;
    int head = blockIdx.x & 15;
    int t = threadIdx.x, warp = t >> 5, lane = t & 31;

    unsigned qb = (unsigned)__cvta_generic_to_shared(sQ);
    unsigned kb = (unsigned)__cvta_generic_to_shared(sK);
    unsigned vb = (unsigned)__cvta_generic_to_shared(sVt);

    size_t base = (size_t)(win * 98) * QKVDIM + head * 32;
    const float* qf = qkvf + base;

    // zero Vt (720 uint4)
    for (int idx = t; idx < 720; idx += 128)
        ((uint4*)sVt)[idx] = make_uint4(0, 0, 0, 0);
    // Q/K: 98 rows x 8 float4 chunks, convert fp32->fp16
    for (int idx = t; idx < 784; idx += 128) {
        int row = idx >> 3, c = idx & 7;
        float4 vq = *(const float4*)(qf + (size_t)row * QKVDIM + c * 4);
        float4 vk = *(const float4*)(qf + 512 + (size_t)row * QKVDIM + c * 4);
        unsigned off = swz64(row, c >> 1) + (c & 1) * 8;
        *(uint2*)((char*)sQ + off) = f4h(vq);
        *(uint2*)((char*)sK + off) = f4h(vk);
    }
    // zero pad rows 98..111
    for (int idx = t; idx < 56; idx += 128) {
        int row = 98 + (idx >> 2), c = idx & 3;
        uint4 z = make_uint4(0, 0, 0, 0);
        *(uint4*)((char*)sQ + swz64(row, c)) = z;
        *(uint4*)((char*)sK + swz64(row, c)) = z;
    }
    __syncthreads();
    // V transpose (scalar) + ones row
    for (int idx = t; idx < 98 * 32; idx += 128) {
        int n = idx >> 5, hd = idx & 31;
        sVt[hd * VTS + n] = f2h(qf[1024 + (size_t)n * QKVDIM + hd]);
    }
    if (t < 98) sVt[32 * VTS + t] = 0x3C00;   // fp16 1.0
    __syncthreads();

    const float CE = 0.25505653517f;          // log2(e)/sqrt(32)
    int mat  = lane >> 3, rsub = lane & 7;
    int q2   = (lane & 3) * 2;
    int r4   = lane >> 2;
    int aRow = (mat & 1) * 8 + rsub;
    int bRow = (mat >> 1) * 8 + rsub;

#pragma unroll
    for (int mi = 0; mi < 2; ++mi) {
        int mt = warp + mi * 4;
        if (mt >= 7) break;

        unsigned Aq[2][4];
#pragma unroll
        for (int kk = 0; kk < 2; ++kk)
            ldsm4(Aq[kk], qb + swz64(mt * 16 + aRow, kk * 2 + (mat >> 1)));

        float S[13][4];
#pragma unroll
        for (int nt = 0; nt < 13; ++nt) {
            S[nt][0] = 0.f; S[nt][1] = 0.f; S[nt][2] = 0.f; S[nt][3] = 0.f;
        }
#pragma unroll
        for (int g = 0; g < 7; ++g)
#pragma unroll
            for (int kk = 0; kk < 2; ++kk) {
                unsigned Bf[4];
                ldsm4(Bf, kb + swz64(g * 16 + bRow, kk * 2 + (mat & 1)));
                mma16(S[2 * g], Aq[kk], &Bf[0]);
                if (2 * g + 1 < 13) mma16(S[2 * g + 1], Aq[kk], &Bf[2]);
            }

        // row max over valid cols
        float mx0 = -1e30f, mx1 = -1e30f;
#pragma unroll
        for (int nt = 0; nt < 12; ++nt) {
            mx0 = fmaxf(mx0, fmaxf(S[nt][0], S[nt][1]));
            mx1 = fmaxf(mx1, fmaxf(S[nt][2], S[nt][3]));
        }
        if (q2 == 0) {     // nt=12: only cols 96,97 valid
            mx0 = fmaxf(mx0, fmaxf(S[12][0], S[12][1]));
            mx1 = fmaxf(mx1, fmaxf(S[12][2], S[12][3]));
        }
        mx0 = fmaxf(mx0, __shfl_xor_sync(0xffffffffu, mx0, 1));
        mx0 = fmaxf(mx0, __shfl_xor_sync(0xffffffffu, mx0, 2));
        mx1 = fmaxf(mx1, __shfl_xor_sync(0xffffffffu, mx1, 1));
        mx1 = fmaxf(mx1, __shfl_xor_sync(0xffffffffu, mx1, 2));
        float mc0 = mx0 * CE, mc1 = mx1 * CE;

        // P = exp2((S - mx)*CE) as fp16x2 fragments
        unsigned P0[13], P1[13];
#pragma unroll
        for (int nt = 0; nt < 13; ++nt) {
            float t00 = S[nt][0] * CE - mc0, t01 = S[nt][1] * CE - mc0;
            float t10 = S[nt][2] * CE - mc1, t11 = S[nt][3] * CE - mc1;
            unsigned u0, u1;
            asm("cvt.rn.f16x2.f32 %0, %1, %2;" : "=r"(u0) : "f"(t01), "f"(t00));
            asm("cvt.rn.f16x2.f32 %0, %1, %2;" : "=r"(u1) : "f"(t11), "f"(t10));
            asm("ex2.approx.f16x2 %0, %1;" : "=r"(u0) : "r"(u0));
            asm("ex2.approx.f16x2 %0, %1;" : "=r"(u1) : "r"(u1));
            if (nt == 12 && q2 != 0) { u0 = 0u; u1 = 0u; }
            P0[nt] = u0; P1[nt] = u1;
        }

        // O = P @ V (+ ones column -> row sums in O4)
        float O0[4][4], O4[4];
#pragma unroll
        for (int j = 0; j < 4; ++j) {
            O0[j][0] = 0.f; O0[j][1] = 0.f; O0[j][2] = 0.f; O0[j][3] = 0.f;
            O4[j] = 0.f;
        }
#pragma unroll
        for (int kt = 0; kt < 7; ++kt) {
            unsigned Av[4];
            Av[0] = P0[2 * kt];
            Av[1] = P1[2 * kt];
            Av[2] = (2 * kt + 1 < 13) ? P0[2 * kt + 1] : 0u;
            Av[3] = (2 * kt + 1 < 13) ? P1[2 * kt + 1] : 0u;
            unsigned cOff = (unsigned)((2 * kt + (mat & 1)) * 16);
            unsigned Bf0[4], Bf1[4], Bf2[4];
            ldsm4(Bf0, vb + (unsigned)(bRow * (VTS * 2)) + cOff);
            ldsm4(Bf1, vb + (unsigned)((16 + bRow) * (VTS * 2)) + cOff);
            ldsm4(Bf2, vb + (unsigned)((32 + bRow) * (VTS * 2)) + cOff);
            mma16(O0[0], Av, &Bf0[0]);
            mma16(O0[1], Av, &Bf0[2]);
            mma16(O0[2], Av, &Bf1[0]);
            mma16(O0[3], Av, &Bf1[2]);
            mma16(O4,    Av, &Bf2[0]);
        }

        // row sums live in col 32 (q2==0 thread's c0/c2); broadcast in quad
        float s0 = __shfl_sync(0xffffffffu, O4[0], lane & ~3);
        float s1 = __shfl_sync(0xffffffffu, O4[2], lane & ~3);
        float inv0 = __fdividef(1.f, s0);
        float inv1 = __fdividef(1.f, s1);

        int row0 = mt * 16 + r4;
        size_t ob = (size_t)(win * 98) * CDIM + head * 32;
#pragma unroll
        for (int j = 0; j < 4; ++j) {
            int col = j * 8 + q2;
            if (row0 < 98) {
                unsigned d;
                float v0 = O0[j][0] * inv0, v1 = O0[j][1] * inv0;
                asm("cvt.rn.f16x2.f32 %0, %1, %2;" : "=r"(d) : "f"(v1), "f"(v0));
                *(unsigned*)(o + ob + (size_t)row0 * CDIM + col) = d;
            }
            if (row0 + 8 < 98) {
                unsigned d;
                float v0 = O0[j][2] * inv1, v1 = O0[j][3] * inv1;
                asm("cvt.rn.f16x2.f32 %0, %1, %2;" : "=r"(d) : "f"(v1), "f"(v0));
                *(unsigned*)(o + ob + (size_t)(row0 + 8) * CDIM + col) = d;
            }
        }
    }
}

// ---------------------------------------------------------------------------
// launch
// ---------------------------------------------------------------------------
extern "C" void kernel_launch(void* const* d_in, const int* in_sizes, int n_in,
                              void* d_out, int out_size)
{
    (void)in_sizes; (void)n_in; (void)out_size;

    const float* x     = (const float*)d_in[0];
    const float* g1    = (const float*)d_in[1];
    const float* b1    = (const float*)d_in[2];
    const float* wqkv  = (const float*)d_in[3];
    const float* bqkv  = (const float*)d_in[4];
    const float* wproj = (const float*)d_in[5];
    const float* bproj = (const float*)d_in[6];
    const float* g2    = (const float*)d_in[7];
    const float* b2    = (const float*)d_in[8];
    const float* w1    = (const float*)d_in[9];
    const float* bm1   = (const float*)d_in[10];
    const float* w2    = (const float*)d_in[11];
    const float* bm2   = (const float*)d_in[12];
    float* out = (float*)d_out;

    u16 *h, *o, *m, *wq, *wp, *w1t, *w2t;
    float *qkv, *attn;
    cudaGetSymbolAddress((void**)&h,    g_h);
    cudaGetSymbolAddress((void**)&qkv,  g_qkv);
    cudaGetSymbolAddress((void**)&o,    g_o);
    cudaGetSymbolAddress((void**)&attn, g_attn);
    cudaGetSymbolAddress((void**)&m,    g_m);
    cudaGetSymbolAddress((void**)&wq,   g_wq);
    cudaGetSymbolAddress((void**)&wp,   g_wp);
    cudaGetSymbolAddress((void**)&w1t,  g_w1);
    cudaGetSymbolAddress((void**)&w2t,  g_w2);

    dim3 wblk(32, 8);
    wconv_kernel<<<dim3(QKVDIM / 32, CDIM / 32), wblk>>>(wqkv, wq, CDIM, QKVDIM);
    wconv_kernel<<<dim3(CDIM / 32, CDIM / 32),   wblk>>>(wproj, wp, CDIM, CDIM);
    wconv_kernel<<<dim3(MLPDIM / 32, CDIM / 32), wblk>>>(w1, w1t, CDIM, MLPDIM);
    wconv_kernel<<<dim3(CDIM / 32, MLPDIM / 32), wblk>>>(w2, w2t, MLPDIM, CDIM);

    const int LN_BLOCKS = TOKENS / 8;
    const int MT = TOKENS / 128;   // 784

    // 1. window-partition gather + LN1 -> h (fp16)
    ln_kernel<<<LN_BLOCKS, 256>>>(x, g1, b1, h, 1);

    // 2. qkv = h @ wqkv + bqkv (fp32)
    gemm_fp16<0><<<dim3(QKVDIM / 128, MT), 256, GEMM_DSM>>>(
        h, wq, bqkv, nullptr, qkv, nullptr, QKVDIM, CDIM);

    // 3. tensor-core windowed attention -> o (fp16)
    attn_kernel<<<NWINHEAD, 128>>>(qkv, o);

    // 4. attn = o @ wproj + bproj (fp32)
    gemm_fp16<0><<<dim3(CDIM / 128, MT), 256, GEMM_DSM>>>(
        o, wp, bproj, nullptr, attn, nullptr, CDIM, CDIM);

    // 5. LN2 -> h (fp16)
    ln_kernel<<<LN_BLOCKS, 256>>>(attn, g2, b2, h, 0);

    // 6. m = gelu(h @ w1 + bm1) (fp16)
    gemm_fp16<1><<<dim3(MLPDIM / 128, MT), 256, GEMM_DSM>>>(
        h, w1t, bm1, nullptr, nullptr, m, MLPDIM, CDIM);

    // 7. out[w2o(r)] = attn[r] + m[r] @ w2 + bm2
    gemm_fp16<2><<<dim3(CDIM / 128, MT), 256, GEMM_DSM>>>(
        m, w2t, bm2, attn, out, nullptr, CDIM, MLPDIM);
}

// round 17
// speedup vs baseline: 2.3371x; 1.0441x over previous
#include <cuda_runtime.h>
#include <cuda_fp16.h>
#include <cstdint>

// ---------------------------------------------------------------------------
// Problem constants
// ---------------------------------------------------------------------------
#define TOKENS   100352          // 1024 windows * 98
#define CDIM     512
#define QKVDIM   1536
#define MLPDIM   2048
#define NWINHEAD 16384

typedef unsigned short u16;

// ---------------------------------------------------------------------------
// Scratch
// ---------------------------------------------------------------------------
__device__ __align__(16) u16   g_h   [(size_t)TOKENS * CDIM];    // LN out fp16
__device__ __align__(16) u16   g_qkv [(size_t)TOKENS * QKVDIM];  // fp16 (rounding
                                                                 // point unchanged)
__device__ __align__(16) u16   g_o   [(size_t)TOKENS * CDIM];    // attn out fp16
__device__ __align__(16) float g_attn[(size_t)TOKENS * CDIM];    // proj out fp32
__device__ __align__(16) u16   g_m   [(size_t)TOKENS * MLPDIM];  // gelu out fp16
__device__ __align__(16) u16   g_wq  [QKVDIM * CDIM];            // [N][K] fp16
__device__ __align__(16) u16   g_wp  [CDIM * CDIM];
__device__ __align__(16) u16   g_w1  [MLPDIM * CDIM];
__device__ __align__(16) u16   g_w2  [CDIM * MLPDIM];

// ---------------------------------------------------------------------------
// helpers
// ---------------------------------------------------------------------------
__device__ __forceinline__ int w2o(int m) {
    int win = m / 98;
    int n   = m - win * 98;
    int b   = win >> 9;
    int r   = win & 511;
    int wd  = r >> 6;
    int wh  = (r >> 3) & 7;
    int ww  = r & 7;
    int dw  = n / 49;
    int rem = n - dw * 49;
    int hw  = rem / 7;
    int wl  = rem - hw * 7;
    return (((b * 16 + wd * 2 + dw) * 56) + wh * 7 + hw) * 56 + ww * 7 + wl;
}

__device__ __forceinline__ u16 f2h(float x) {
    __half h = __float2half_rn(x);
    return *reinterpret_cast<u16*>(&h);
}

__device__ __forceinline__ float gelu_tanh(float x) {
    float u = 0.7978845608028654f * (x + 0.044715f * x * x * x);
    return 0.5f * x * (1.f + tanhf(u));
}

__device__ __forceinline__ void cpasync16(unsigned dst, const void* src) {
    asm volatile("cp.async.cg.shared.global [%0], [%1], 16;" :: "r"(dst), "l"(src));
}

__device__ __forceinline__ void ldsm4(unsigned r[4], unsigned addr) {
    asm volatile("ldmatrix.sync.aligned.m8n8.x4.shared.b16 {%0,%1,%2,%3}, [%4];"
                 : "=r"(r[0]), "=r"(r[1]), "=r"(r[2]), "=r"(r[3]) : "r"(addr));
}

__device__ __forceinline__ void mma16(float c[4], const unsigned a[4], const unsigned b[2]) {
    asm volatile(
        "mma.sync.aligned.m16n8k16.row.col.f32.f16.f16.f32 "
        "{%0,%1,%2,%3},{%4,%5,%6,%7},{%8,%9},{%0,%1,%2,%3};"
        : "+f"(c[0]), "+f"(c[1]), "+f"(c[2]), "+f"(c[3])
        : "r"(a[0]), "r"(a[1]), "r"(a[2]), "r"(a[3]), "r"(b[0]), "r"(b[1]));
}

__device__ __forceinline__ unsigned swz64(int row, int c) {
    return (unsigned)(row * 64 + ((c ^ ((row >> 1) & 3)) << 4));
}

// ---------------------------------------------------------------------------
// Weight convert + transpose: w[K][N] fp32 -> [N][K] fp16
// ---------------------------------------------------------------------------
__global__ void wconv_kernel(const float* __restrict__ w, u16* __restrict__ wt,
                             int K, int N)
{
    __shared__ float tile[32][33];
    int n0 = blockIdx.x * 32, k0 = blockIdx.y * 32;
    int tx = threadIdx.x, ty = threadIdx.y;
#pragma unroll
    for (int r = 0; r < 4; ++r)
        tile[ty + 8 * r][tx] = w[(size_t)(k0 + ty + 8 * r) * N + n0 + tx];
    __syncthreads();
#pragma unroll
    for (int r = 0; r < 4; ++r) {
        int n = n0 + ty + 8 * r, k = k0 + tx;
        wt[(size_t)n * K + k] = f2h(tile[tx][ty + 8 * r]);
    }
}

// ---------------------------------------------------------------------------
// LayerNorm -> fp16
// ---------------------------------------------------------------------------
__global__ void ln_kernel(const float* __restrict__ x, const float* __restrict__ g,
                          const float* __restrict__ b, u16* __restrict__ o,
                          int gather)
{
    int row  = blockIdx.x * 8 + (threadIdx.x >> 5);
    int lane = threadIdx.x & 31;
    if (row >= TOKENS) return;
    int src = gather ? w2o(row) : row;
    const float* xr = x + (size_t)src * CDIM;

    float v[16], s = 0.f, ss = 0.f;
#pragma unroll
    for (int k = 0; k < 16; ++k) {
        float a = xr[lane + 32 * k];
        v[k] = a; s += a; ss += a * a;
    }
#pragma unroll
    for (int off = 16; off; off >>= 1) {
        s  += __shfl_xor_sync(0xffffffffu, s,  off);
        ss += __shfl_xor_sync(0xffffffffu, ss, off);
    }
    float mu   = s * (1.f / 512.f);
    float rstd = rsqrtf(ss * (1.f / 512.f) - mu * mu + 1e-5f);

    size_t ro = (size_t)row * CDIM;
#pragma unroll
    for (int k = 0; k < 16; ++k) {
        int c = lane + 32 * k;
        o[ro + c] = f2h((v[k] - mu) * rstd * g[c] + b[c]);
    }
}

// ---------------------------------------------------------------------------
// FP16 single-pass GEMM (R14 skeleton):
// 128x128 tile, BK=32, 3-stage cp.async, 256 thr, warps 2x4, wt 64x32.
// ---------------------------------------------------------------------------
#define STG16    16384
#define OFF_B    8192
#define GEMM_DSM (3 * STG16)

__device__ __forceinline__ void load_stage(unsigned sb,
    const u16* __restrict__ A, const u16* __restrict__ B,
    int K, int bm, int bn, int kt, int t)
{
#pragma unroll
    for (int i = 0; i < 2; ++i) {
        int ch = t * 2 + i;
        int row = ch >> 2, c = ch & 3;
        unsigned so = swz64(row, c);
        cpasync16(sb + so,         A + (size_t)(bm + row) * K + kt * 32 + c * 8);
        cpasync16(sb + OFF_B + so, B + (size_t)(bn + row) * K + kt * 32 + c * 8);
    }
}

__device__ __forceinline__ void compute_k16(unsigned base, int kk,
                                            int wm, int wn, int lane, float c[4][4][4])
{
    int mat  = lane >> 3;
    int rsub = lane & 7;
    int aRow = (mat & 1) * 8 + rsub;  int aCh = kk * 2 + (mat >> 1);
    int bRow = (mat >> 1) * 8 + rsub; int bCh = kk * 2 + (mat & 1);

    unsigned A[4][4], B[2][4];
#pragma unroll
    for (int i = 0; i < 4; ++i)
        ldsm4(A[i], base + swz64(wm * 64 + i * 16 + aRow, aCh));
#pragma unroll
    for (int g = 0; g < 2; ++g)
        ldsm4(B[g], base + OFF_B + swz64(wn * 32 + g * 16 + bRow, bCh));
#pragma unroll
    for (int i = 0; i < 4; ++i)
#pragma unroll
        for (int j = 0; j < 4; ++j)
            mma16(c[i][j], A[i], &B[j >> 1][(j & 1) * 2]);
}

// EPI: 0 = +bias -> fp32 ; 1 = +bias,gelu -> fp16 ; 2 = +bias+res, w2o scatter ;
// EPI: 3 = +bias -> fp16 (packed f16x2 store; rounding identical to attention's
//          former load-time cvt, so qkv numerics are unchanged)
template <int EPI>
__global__ void __launch_bounds__(256, 2)
gemm_fp16(const u16* __restrict__ A, const u16* __restrict__ B,
          const float* __restrict__ bias, const float* __restrict__ res,
          float* __restrict__ Cf, u16* __restrict__ Ch,
          int N, int K)
{
    extern __shared__ char sm_raw[];
    unsigned sb = (unsigned)__cvta_generic_to_shared(sm_raw);

    int t = threadIdx.x;
    int warp = t >> 5, lane = t & 31;
    int wm = warp >> 2, wn = warp & 3;
    int bm = blockIdx.y * 128, bn = blockIdx.x * 128;

    float c[4][4][4];
#pragma unroll
    for (int i = 0; i < 4; ++i)
#pragma unroll
        for (int j = 0; j < 4; ++j)
#pragma unroll
            for (int k = 0; k < 4; ++k) c[i][j][k] = 0.f;

    int KT = K >> 5;
    load_stage(sb,         A, B, K, bm, bn, 0, t);
    asm volatile("cp.async.commit_group;" ::: "memory");
    load_stage(sb + STG16, A, B, K, bm, bn, 1, t);
    asm volatile("cp.async.commit_group;" ::: "memory");

    for (int kt = 0; kt < KT; ++kt) {
        if (kt + 1 < KT) asm volatile("cp.async.wait_group 1;" ::: "memory");
        else             asm volatile("cp.async.wait_group 0;" ::: "memory");
        __syncthreads();
        if (kt + 2 < KT) {
            load_stage(sb + (unsigned)((kt + 2) % 3) * STG16,
                       A, B, K, bm, bn, kt + 2, t);
            asm volatile("cp.async.commit_group;" ::: "memory");
        }
        unsigned base = sb + (unsigned)(kt % 3) * STG16;
        compute_k16(base, 0, wm, wn, lane, c);
        compute_k16(base, 1, wm, wn, lane, c);
    }

#pragma unroll
    for (int i = 0; i < 4; ++i) {
        int r0 = bm + wm * 64 + i * 16 + (lane >> 2);
        int rows[2] = { r0, r0 + 8 };
        int dst[2];
        if (EPI == 2) { dst[0] = w2o(rows[0]); dst[1] = w2o(rows[1]); }
#pragma unroll
        for (int j = 0; j < 4; ++j) {
            int col = bn + wn * 32 + j * 8 + ((lane & 3) << 1);
            float bv0 = bias[col], bv1 = bias[col + 1];
#pragma unroll
            for (int rr = 0; rr < 2; ++rr) {
                float v0 = c[i][j][rr * 2 + 0] + bv0;
                float v1 = c[i][j][rr * 2 + 1] + bv1;
                if (EPI == 0) {
                    size_t oo = (size_t)rows[rr] * (size_t)N + col;
                    Cf[oo] = v0; Cf[oo + 1] = v1;
                } else if (EPI == 1) {
                    size_t oo = (size_t)rows[rr] * (size_t)N + col;
                    Ch[oo]     = f2h(gelu_tanh(v0));
                    Ch[oo + 1] = f2h(gelu_tanh(v1));
                } else if (EPI == 3) {
                    unsigned d;
                    asm("cvt.rn.f16x2.f32 %0, %1, %2;" : "=r"(d) : "f"(v1), "f"(v0));
                    size_t oo = (size_t)rows[rr] * (size_t)N + col;
                    *reinterpret_cast<unsigned*>(Ch + oo) = d;
                } else {
                    size_t ro = (size_t)rows[rr] * CDIM + col;
                    v0 += res[ro]; v1 += res[ro + 1];
                    size_t oo = (size_t)dst[rr] * CDIM + col;
                    Cf[oo] = v0; Cf[oo + 1] = v1;
                }
            }
        }
    }
}

// ---------------------------------------------------------------------------
// Tensor-core windowed attention (R16, qkv now fp16 in gmem -> direct uint4
// copies into swizzled smem, no conversion). CTA = (window, head), 128 thr.
// ---------------------------------------------------------------------------
#define VTS 120   // Vt row stride (fp16 elems)

__global__ void __launch_bounds__(128)
attn_kernel(const u16* __restrict__ qkvh, u16* __restrict__ o)
{
    __shared__ __align__(16) u16 sQ[112 * 32];
    __shared__ __align__(16) u16 sK[112 * 32];
    __shared__ __align__(16) u16 sVt[48 * VTS];   // rows 0-31: V^T, row 32: ones

    int win  = blockIdx.x >> 4;
    int head = blockIdx.x & 15;
    int t = threadIdx.x, warp = t >> 5, lane = t & 31;

    unsigned qb = (unsigned)__cvta_generic_to_shared(sQ);
    unsigned kb = (unsigned)__cvta_generic_to_shared(sK);
    unsigned vb = (unsigned)__cvta_generic_to_shared(sVt);

    size_t base = (size_t)(win * 98) * QKVDIM + head * 32;
    const u16* qf = qkvh + base;

    // zero Vt (720 uint4)
    for (int idx = t; idx < 720; idx += 128)
        ((uint4*)sVt)[idx] = make_uint4(0, 0, 0, 0);
    // Q/K: 98 rows x 4 16B chunks, direct copy
    for (int idx = t; idx < 392; idx += 128) {
        int row = idx >> 2, c = idx & 3;
        uint4 vq = *(const uint4*)(qf + (size_t)row * QKVDIM + c * 8);
        uint4 vk = *(const uint4*)(qf + 512 + (size_t)row * QKVDIM + c * 8);
        unsigned off = swz64(row, c);
        *(uint4*)((char*)sQ + off) = vq;
        *(uint4*)((char*)sK + off) = vk;
    }
    // zero pad rows 98..111
    for (int idx = t; idx < 56; idx += 128) {
        int row = 98 + (idx >> 2), c = idx & 3;
        uint4 z = make_uint4(0, 0, 0, 0);
        *(uint4*)((char*)sQ + swz64(row, c)) = z;
        *(uint4*)((char*)sK + swz64(row, c)) = z;
    }
    __syncthreads();
    // V transpose (scalar) + ones row
    for (int idx = t; idx < 98 * 32; idx += 128) {
        int n = idx >> 5, hd = idx & 31;
        sVt[hd * VTS + n] = qf[1024 + (size_t)n * QKVDIM + hd];
    }
    if (t < 98) sVt[32 * VTS + t] = 0x3C00;   // fp16 1.0
    __syncthreads();

    const float CE = 0.25505653517f;          // log2(e)/sqrt(32)
    int mat  = lane >> 3, rsub = lane & 7;
    int q2   = (lane & 3) * 2;
    int r4   = lane >> 2;
    int aRow = (mat & 1) * 8 + rsub;
    int bRow = (mat >> 1) * 8 + rsub;

#pragma unroll
    for (int mi = 0; mi < 2; ++mi) {
        int mt = warp + mi * 4;
        if (mt >= 7) break;

        unsigned Aq[2][4];
#pragma unroll
        for (int kk = 0; kk < 2; ++kk)
            ldsm4(Aq[kk], qb + swz64(mt * 16 + aRow, kk * 2 + (mat >> 1)));

        float S[13][4];
#pragma unroll
        for (int nt = 0; nt < 13; ++nt) {
            S[nt][0] = 0.f; S[nt][1] = 0.f; S[nt][2] = 0.f; S[nt][3] = 0.f;
        }
#pragma unroll
        for (int g = 0; g < 7; ++g)
#pragma unroll
            for (int kk = 0; kk < 2; ++kk) {
                unsigned Bf[4];
                ldsm4(Bf, kb + swz64(g * 16 + bRow, kk * 2 + (mat & 1)));
                mma16(S[2 * g], Aq[kk], &Bf[0]);
                if (2 * g + 1 < 13) mma16(S[2 * g + 1], Aq[kk], &Bf[2]);
            }

        // row max over valid cols
        float mx0 = -1e30f, mx1 = -1e30f;
#pragma unroll
        for (int nt = 0; nt < 12; ++nt) {
            mx0 = fmaxf(mx0, fmaxf(S[nt][0], S[nt][1]));
            mx1 = fmaxf(mx1, fmaxf(S[nt][2], S[nt][3]));
        }
        if (q2 == 0) {     // nt=12: only cols 96,97 valid
            mx0 = fmaxf(mx0, fmaxf(S[12][0], S[12][1]));
            mx1 = fmaxf(mx1, fmaxf(S[12][2], S[12][3]));
        }
        mx0 = fmaxf(mx0, __shfl_xor_sync(0xffffffffu, mx0, 1));
        mx0 = fmaxf(mx0, __shfl_xor_sync(0xffffffffu, mx0, 2));
        mx1 = fmaxf(mx1, __shfl_xor_sync(0xffffffffu, mx1, 1));
        mx1 = fmaxf(mx1, __shfl_xor_sync(0xffffffffu, mx1, 2));
        float mc0 = mx0 * CE, mc1 = mx1 * CE;

        // P = exp2((S - mx)*CE) as fp16x2 fragments
        unsigned P0[13], P1[13];
#pragma unroll
        for (int nt = 0; nt < 13; ++nt) {
            float t00 = S[nt][0] * CE - mc0, t01 = S[nt][1] * CE - mc0;
            float t10 = S[nt][2] * CE - mc1, t11 = S[nt][3] * CE - mc1;
            unsigned u0, u1;
            asm("cvt.rn.f16x2.f32 %0, %1, %2;" : "=r"(u0) : "f"(t01), "f"(t00));
            asm("cvt.rn.f16x2.f32 %0, %1, %2;" : "=r"(u1) : "f"(t11), "f"(t10));
            asm("ex2.approx.f16x2 %0, %1;" : "=r"(u0) : "r"(u0));
            asm("ex2.approx.f16x2 %0, %1;" : "=r"(u1) : "r"(u1));
            if (nt == 12 && q2 != 0) { u0 = 0u; u1 = 0u; }
            P0[nt] = u0; P1[nt] = u1;
        }

        // O = P @ V (+ ones column -> row sums in O4)
        float O0[4][4], O4[4];
#pragma unroll
        for (int j = 0; j < 4; ++j) {
            O0[j][0] = 0.f; O0[j][1] = 0.f; O0[j][2] = 0.f; O0[j][3] = 0.f;
            O4[j] = 0.f;
        }
#pragma unroll
        for (int kt = 0; kt < 7; ++kt) {
            unsigned Av[4];
            Av[0] = P0[2 * kt];
            Av[1] = P1[2 * kt];
            Av[2] = (2 * kt + 1 < 13) ? P0[2 * kt + 1] : 0u;
            Av[3] = (2 * kt + 1 < 13) ? P1[2 * kt + 1] : 0u;
            unsigned cOff = (unsigned)((2 * kt + (mat & 1)) * 16);
            unsigned Bf0[4], Bf1[4], Bf2[4];
            ldsm4(Bf0, vb + (unsigned)(bRow * (VTS * 2)) + cOff);
            ldsm4(Bf1, vb + (unsigned)((16 + bRow) * (VTS * 2)) + cOff);
            ldsm4(Bf2, vb + (unsigned)((32 + bRow) * (VTS * 2)) + cOff);
            mma16(O0[0], Av, &Bf0[0]);
            mma16(O0[1], Av, &Bf0[2]);
            mma16(O0[2], Av, &Bf1[0]);
            mma16(O0[3], Av, &Bf1[2]);
            mma16(O4,    Av, &Bf2[0]);
        }

        // row sums live in col 32 (q2==0 thread's c0/c2); broadcast in quad
        float s0 = __shfl_sync(0xffffffffu, O4[0], lane & ~3);
        float s1 = __shfl_sync(0xffffffffu, O4[2], lane & ~3);
        float inv0 = __fdividef(1.f, s0);
        float inv1 = __fdividef(1.f, s1);

        int row0 = mt * 16 + r4;
        size_t ob = (size_t)(win * 98) * CDIM + head * 32;
#pragma unroll
        for (int j = 0; j < 4; ++j) {
            int col = j * 8 + q2;
            if (row0 < 98) {
                unsigned d;
                float v0 = O0[j][0] * inv0, v1 = O0[j][1] * inv0;
                asm("cvt.rn.f16x2.f32 %0, %1, %2;" : "=r"(d) : "f"(v1), "f"(v0));
                *(unsigned*)(o + ob + (size_t)row0 * CDIM + col) = d;
            }
            if (row0 + 8 < 98) {
                unsigned d;
                float v0 = O0[j][2] * inv1, v1 = O0[j][3] * inv1;
                asm("cvt.rn.f16x2.f32 %0, %1, %2;" : "=r"(d) : "f"(v1), "f"(v0));
                *(unsigned*)(o + ob + (size_t)(row0 + 8) * CDIM + col) = d;
            }
        }
    }
}

// ---------------------------------------------------------------------------
// launch
// ---------------------------------------------------------------------------
extern "C" void kernel_launch(void* const* d_in, const int* in_sizes, int n_in,
                              void* d_out, int out_size)
{
    (void)in_sizes; (void)n_in; (void)out_size;

    const float* x     = (const float*)d_in[0];
    const float* g1    = (const float*)d_in[1];
    const float* b1    = (const float*)d_in[2];
    const float* wqkv  = (const float*)d_in[3];
    const float* bqkv  = (const float*)d_in[4];
    const float* wproj = (const float*)d_in[5];
    const float* bproj = (const float*)d_in[6];
    const float* g2    = (const float*)d_in[7];
    const float* b2    = (const float*)d_in[8];
    const float* w1    = (const float*)d_in[9];
    const float* bm1   = (const float*)d_in[10];
    const float* w2    = (const float*)d_in[11];
    const float* bm2   = (const float*)d_in[12];
    float* out = (float*)d_out;

    u16 *h, *qkv, *o, *m, *wq, *wp, *w1t, *w2t;
    float *attn;
    cudaGetSymbolAddress((void**)&h,    g_h);
    cudaGetSymbolAddress((void**)&qkv,  g_qkv);
    cudaGetSymbolAddress((void**)&o,    g_o);
    cudaGetSymbolAddress((void**)&attn, g_attn);
    cudaGetSymbolAddress((void**)&m,    g_m);
    cudaGetSymbolAddress((void**)&wq,   g_wq);
    cudaGetSymbolAddress((void**)&wp,   g_wp);
    cudaGetSymbolAddress((void**)&w1t,  g_w1);
    cudaGetSymbolAddress((void**)&w2t,  g_w2);

    dim3 wblk(32, 8);
    wconv_kernel<<<dim3(QKVDIM / 32, CDIM / 32), wblk>>>(wqkv, wq, CDIM, QKVDIM);
    wconv_kernel<<<dim3(CDIM / 32, CDIM / 32),   wblk>>>(wproj, wp, CDIM, CDIM);
    wconv_kernel<<<dim3(MLPDIM / 32, CDIM / 32), wblk>>>(w1, w1t, CDIM, MLPDIM);
    wconv_kernel<<<dim3(CDIM / 32, MLPDIM / 32), wblk>>>(w2, w2t, MLPDIM, CDIM);

    const int LN_BLOCKS = TOKENS / 8;
    const int MT = TOKENS / 128;   // 784

    // 1. window-partition gather + LN1 -> h (fp16)
    ln_kernel<<<LN_BLOCKS, 256>>>(x, g1, b1, h, 1);

    // 2. qkv = h @ wqkv + bqkv (fp16 out; EPI 3)
    gemm_fp16<3><<<dim3(QKVDIM / 128, MT), 256, GEMM_DSM>>>(
        h, wq, bqkv, nullptr, nullptr, qkv, QKVDIM, CDIM);

    // 3. tensor-core windowed attention -> o (fp16)
    attn_kernel<<<NWINHEAD, 128>>>(qkv, o);

    // 4. attn = o @ wproj + bproj (fp32)
    gemm_fp16<0><<<dim3(CDIM / 128, MT), 256, GEMM_DSM>>>(
        o, wp, bproj, nullptr, attn, nullptr, CDIM, CDIM);

    // 5. LN2 -> h (fp16)
    ln_kernel<<<LN_BLOCKS, 256>>>(attn, g2, b2, h, 0);

    // 6. m = gelu(h @ w1 + bm1) (fp16)
    gemm_fp16<1><<<dim3(MLPDIM / 128, MT), 256, GEMM_DSM>>>(
        h, w1t, bm1, nullptr, nullptr, m, MLPDIM, CDIM);

    // 7. out[w2o(r)] = attn[r] + m[r] @ w2 + bm2
    gemm_fp16<2><<<dim3(CDIM / 128, MT), 256, GEMM_DSM>>>(
        m, w2t, bm2, attn, out, nullptr, CDIM, MLPDIM);
}